// round 2
// baseline (speedup 1.0000x reference)
#include <cuda_runtime.h>
#include <math_constants.h>

// Problem constants
#define Bn  8
#define Sn  1024
#define Dn  1024
#define Hn  16
#define DHn 64
#define Mn  (Bn * Sn)   // 8192

// Scratch (device globals: allocation-free per harness rules)
__device__ float g_q[Bn * Hn * Sn * DHn];   // [B,H,S,DH]
__device__ float g_k[Bn * Hn * Sn * DHn];
__device__ float g_v[Bn * Hn * Sn * DHn];
__device__ float g_ctx[Bn * Sn * Dn];       // [B,S,D]

// ---------------------------------------------------------------------------
// SGEMM (NT): C = A[M,K] @ W[N,K]^T + bias, fp32.
// mode 0: write to [B,H,S,DH] head layout, scaled by `scale`
// mode 2: write plain [M,N]
// 128x128 block tile, 256 threads, 8x8 per-thread micro-tile, BK=8.
// ---------------------------------------------------------------------------
__global__ __launch_bounds__(256)
void sgemm_nt(const float* __restrict__ A, const float* __restrict__ W,
              const float* __restrict__ bias, float* __restrict__ C,
              int mode, float scale)
{
    __shared__ float As[8][128];
    __shared__ float Bs[8][128];

    const int tid = threadIdx.x;
    const int m0 = blockIdx.y * 128;
    const int n0 = blockIdx.x * 128;
    const int ty = tid >> 4;        // 0..15
    const int tx = tid & 15;        // 0..15

    const int lr = tid >> 1;        // 0..127
    const int lc = (tid & 1) * 4;   // 0 or 4

    const float* Aptr = A + (size_t)(m0 + lr) * Dn + lc;
    const float* Wptr = W + (size_t)(n0 + lr) * Dn + lc;

    float acc[8][8];
    #pragma unroll
    for (int i = 0; i < 8; i++)
        #pragma unroll
        for (int j = 0; j < 8; j++) acc[i][j] = 0.f;

    for (int k0 = 0; k0 < Dn; k0 += 8) {
        float4 av = *(const float4*)(Aptr + k0);
        float4 wv = *(const float4*)(Wptr + k0);
        As[lc + 0][lr] = av.x; As[lc + 1][lr] = av.y;
        As[lc + 2][lr] = av.z; As[lc + 3][lr] = av.w;
        Bs[lc + 0][lr] = wv.x; Bs[lc + 1][lr] = wv.y;
        Bs[lc + 2][lr] = wv.z; Bs[lc + 3][lr] = wv.w;
        __syncthreads();

        #pragma unroll
        for (int kk = 0; kk < 8; kk++) {
            float a[8], b[8];
            *(float4*)(&a[0]) = *(const float4*)(&As[kk][ty * 8]);
            *(float4*)(&a[4]) = *(const float4*)(&As[kk][ty * 8 + 4]);
            *(float4*)(&b[0]) = *(const float4*)(&Bs[kk][tx * 8]);
            *(float4*)(&b[4]) = *(const float4*)(&Bs[kk][tx * 8 + 4]);
            #pragma unroll
            for (int i = 0; i < 8; i++)
                #pragma unroll
                for (int j = 0; j < 8; j++)
                    acc[i][j] += a[i] * b[j];
        }
        __syncthreads();
    }

    // Epilogue
    #pragma unroll
    for (int i = 0; i < 8; i++) {
        const int m = m0 + ty * 8 + i;
        const int bb = m >> 10;        // m / S
        const int s  = m & 1023;       // m % S
        #pragma unroll
        for (int j = 0; j < 8; j++) {
            const int n = n0 + tx * 8 + j;
            float val = (acc[i][j] + bias[n]) * scale;
            if (mode == 2) {
                C[(size_t)m * Dn + n] = val;
            } else {
                const int h = n >> 6;   // n / DH
                const int d = n & 63;   // n % DH
                C[(((size_t)(bb * Hn + h) * Sn + s) * DHn) + d] = val;
            }
        }
    }
}

// ---------------------------------------------------------------------------
// Fused flash-style attention.
// Grid: (S/256, H, B), 256 threads. Each thread owns ONE query row:
// q[64] and o[64] in registers, thread-local online softmax.
// K/V staged as 64-row tiles in smem (broadcast reads). Mask tile staged from
// INT32 gmem (harness serializes bool as int32) packed to bytes in smem.
// Last head: p *= graph, normalize by sum(p*g) (ref's +1e-9 is ~2e-9 rel).
// ---------------------------------------------------------------------------
__global__ __launch_bounds__(256)
void attn_kernel(const float* __restrict__ q, const float* __restrict__ k,
                 const float* __restrict__ v,
                 const int* __restrict__ mask,
                 const float* __restrict__ graph,
                 float* __restrict__ ctx)
{
    __shared__ float4 Ks[64][16];            // 16 KB
    __shared__ float4 Vs[64][16];            // 16 KB
    __shared__ unsigned char Ms[256][64];    // 16 KB

    const int tid = threadIdx.x;
    const int h = blockIdx.y;
    const int b = blockIdx.z;
    const int q0 = blockIdx.x * 256;
    const int row = q0 + tid;

    const float* qrow = q + ((size_t)((b * Hn + h) * Sn) + row) * DHn;
    float4 qv[16];
    #pragma unroll
    for (int i = 0; i < 16; i++) qv[i] = ((const float4*)qrow)[i];

    float4 ov[16];
    #pragma unroll
    for (int i = 0; i < 16; i++) ov[i] = make_float4(0.f, 0.f, 0.f, 0.f);

    float mx = -1e30f;
    float l = 0.f;

    const float* kbase = k + (size_t)((b * Hn + h) * Sn) * DHn;
    const float* vbase = v + (size_t)((b * Hn + h) * Sn) * DHn;
    const int* mbase = mask + (size_t)(b * Sn) * Sn;
    const bool lastH = (h == Hn - 1);
    const float* gbase = graph + ((size_t)(b * Sn) + row) * Sn;

    for (int kt = 0; kt < Sn; kt += 64) {
        // Stage K/V tile (64 rows x 64 floats = 1024 float4 each)
        const float4* ksrc = (const float4*)(kbase + (size_t)kt * DHn);
        const float4* vsrc = (const float4*)(vbase + (size_t)kt * DHn);
        #pragma unroll
        for (int i = 0; i < 4; i++) {
            int f = i * 256 + tid;
            ((float4*)Ks)[f] = ksrc[f];
            ((float4*)Vs)[f] = vsrc[f];
        }
        // Stage mask tile: 256 rows x 64 int32 -> packed bytes.
        // 256*64/4 = 4096 int4 reads; 16 per thread.
        #pragma unroll
        for (int i = 0; i < 16; i++) {
            int idx = i * 256 + tid;      // 0..4095, int4 granules
            int r = idx >> 4;             // 16 int4 per row
            int c = (idx & 15) * 4;       // starting key col
            int4 mv = *(const int4*)(mbase + (size_t)(q0 + r) * Sn + kt + c);
            uchar4 pk;
            pk.x = (unsigned char)(mv.x != 0);
            pk.y = (unsigned char)(mv.y != 0);
            pk.z = (unsigned char)(mv.z != 0);
            pk.w = (unsigned char)(mv.w != 0);
            *(uchar4*)&Ms[r][c] = pk;
        }
        __syncthreads();

        #pragma unroll 2
        for (int j = 0; j < 64; j++) {
            // dot(q, k_j) with 4 partial accumulators
            float s0 = 0.f, s1 = 0.f, s2 = 0.f, s3 = 0.f;
            #pragma unroll
            for (int i = 0; i < 16; i++) {
                float4 kv = Ks[j][i];
                s0 += qv[i].x * kv.x;
                s1 += qv[i].y * kv.y;
                s2 += qv[i].z * kv.z;
                s3 += qv[i].w * kv.w;
            }
            float s = (s0 + s1) + (s2 + s3);
            if (Ms[tid][j]) s = -CUDART_INF_F;   // masked out -> weight 0

            float p;
            if (s > mx) {
                float f = __expf(mx - s);
                l *= f;
                #pragma unroll
                for (int i = 0; i < 16; i++) {
                    ov[i].x *= f; ov[i].y *= f; ov[i].z *= f; ov[i].w *= f;
                }
                mx = s;
                p = 1.f;
            } else {
                p = __expf(s - mx);   // exp(-inf) = 0 for masked
            }
            if (lastH) p *= gbase[kt + j];

            l += p;
            #pragma unroll
            for (int i = 0; i < 16; i++) {
                float4 vv = Vs[j][i];
                ov[i].x += p * vv.x;
                ov[i].y += p * vv.y;
                ov[i].z += p * vv.z;
                ov[i].w += p * vv.w;
            }
        }
        __syncthreads();
    }

    const float inv = 1.f / l;
    float* obase = ctx + ((size_t)(b * Sn) + row) * Dn + h * DHn;
    #pragma unroll
    for (int i = 0; i < 16; i++) {
        float4 r;
        r.x = ov[i].x * inv; r.y = ov[i].y * inv;
        r.z = ov[i].z * inv; r.w = ov[i].w * inv;
        ((float4*)obase)[i] = r;
    }
}

// ---------------------------------------------------------------------------
// Launch
// ---------------------------------------------------------------------------
extern "C" void kernel_launch(void* const* d_in, const int* in_sizes, int n_in,
                              void* d_out, int out_size)
{
    const float* key   = (const float*)d_in[0];
    const float* value = (const float*)d_in[1];
    const float* query = (const float*)d_in[2];
    const int*   mask  = (const int*)d_in[3];
    const float* graph = (const float*)d_in[4];
    const float* Wq = (const float*)d_in[5];
    const float* bq = (const float*)d_in[6];
    const float* Wk = (const float*)d_in[7];
    const float* bk = (const float*)d_in[8];
    const float* Wv = (const float*)d_in[9];
    const float* bv = (const float*)d_in[10];
    const float* Wo = (const float*)d_in[11];
    const float* bo = (const float*)d_in[12];
    float* out = (float*)d_out;

    void *qp, *kp, *vp, *cp;
    cudaGetSymbolAddress(&qp, g_q);
    cudaGetSymbolAddress(&kp, g_k);
    cudaGetSymbolAddress(&vp, g_v);
    cudaGetSymbolAddress(&cp, g_ctx);

    dim3 ggrid(Dn / 128, Mn / 128);   // (8, 64)
    sgemm_nt<<<ggrid, 256>>>(query, Wq, bq, (float*)qp, 0, 0.125f);  // 1/sqrt(64)
    sgemm_nt<<<ggrid, 256>>>(key,   Wk, bk, (float*)kp, 0, 1.0f);
    sgemm_nt<<<ggrid, 256>>>(value, Wv, bv, (float*)vp, 0, 1.0f);

    attn_kernel<<<dim3(Sn / 256, Hn, Bn), 256>>>(
        (const float*)qp, (const float*)kp, (const float*)vp,
        mask, graph, (float*)cp);

    sgemm_nt<<<ggrid, 256>>>((const float*)cp, Wo, bo, out, 2, 1.0f);
}

// round 4
// speedup vs baseline: 2.8455x; 2.8455x over previous
#include <cuda_runtime.h>
#include <cuda_bf16.h>
#include <math_constants.h>

#define Bn  8
#define Sn  1024
#define Dn  1024
#define Hn  16
#define DHn 64
#define Mn  (Bn * Sn)   // 8192

// Scratch (device globals)
__device__ float g_q[Bn * Hn * Sn * DHn];   // [B,H,S,DH]
__device__ float g_k[Bn * Hn * Sn * DHn];
__device__ float g_v[Bn * Hn * Sn * DHn];
__device__ float g_ctx[Bn * Sn * Dn];       // [B,S,D]

// ---------------------------------------------------------------------------
// helpers
// ---------------------------------------------------------------------------
__device__ __forceinline__ unsigned smem_u32(const void* p) {
    return (unsigned)__cvta_generic_to_shared(p);
}

__device__ __forceinline__ void mma16816(float* c, const unsigned* a, const unsigned* b) {
    asm volatile(
        "mma.sync.aligned.m16n8k16.row.col.f32.bf16.bf16.f32 "
        "{%0,%1,%2,%3},{%4,%5,%6,%7},{%8,%9},{%0,%1,%2,%3};\n"
        : "+f"(c[0]), "+f"(c[1]), "+f"(c[2]), "+f"(c[3])
        : "r"(a[0]), "r"(a[1]), "r"(a[2]), "r"(a[3]), "r"(b[0]), "r"(b[1]));
}
__device__ __forceinline__ void ldsm4(unsigned* r, unsigned addr) {
    asm volatile("ldmatrix.sync.aligned.m8n8.x4.shared.b16 {%0,%1,%2,%3},[%4];\n"
                 : "=r"(r[0]), "=r"(r[1]), "=r"(r[2]), "=r"(r[3]) : "r"(addr));
}
__device__ __forceinline__ void ldsm2(unsigned* r, unsigned addr) {
    asm volatile("ldmatrix.sync.aligned.m8n8.x2.shared.b16 {%0,%1},[%2];\n"
                 : "=r"(r[0]), "=r"(r[1]) : "r"(addr));
}
// split two fp32 into bf16 hi-pair and lo-pair (packed words, elem0 in low half)
__device__ __forceinline__ void split_pack(float x, float y, unsigned& hi, unsigned& lo) {
    __nv_bfloat16 hx = __float2bfloat16(x);
    __nv_bfloat16 hy = __float2bfloat16(y);
    float rx = x - __bfloat162float(hx);
    float ry = y - __bfloat162float(hy);
    __nv_bfloat162 h; h.x = hx; h.y = hy;
    __nv_bfloat162 l; l.x = __float2bfloat16(rx); l.y = __float2bfloat16(ry);
    hi = *(unsigned*)&h;
    lo = *(unsigned*)&l;
}

// ---------------------------------------------------------------------------
// Split-bf16 (3x) GEMM: C = A[M,K] @ W[N,K]^T + bias, fp32 in/out.
// Block 128x128, BK=32, 256 threads, warp grid 2x4 (warp tile 64x32).
// mode 0: head-split output [B,H,S,DH], scaled. mode 2: plain [M,N].
// ---------------------------------------------------------------------------
#define GSTW 20   // words per smem row (32 bf16 data + 8 bf16 pad)

__global__ __launch_bounds__(256)
void gemm_bf16x3(const float* __restrict__ A, const float* __restrict__ W,
                 const float* __restrict__ bias, float* __restrict__ C,
                 int mode, float scale)
{
    __shared__ __align__(16) unsigned sAhi[128 * GSTW];
    __shared__ __align__(16) unsigned sAlo[128 * GSTW];
    __shared__ __align__(16) unsigned sWhi[128 * GSTW];
    __shared__ __align__(16) unsigned sWlo[128 * GSTW];

    const int tid = threadIdx.x;
    const int m0 = blockIdx.y * 128, n0 = blockIdx.x * 128;
    const int wid = tid >> 5, lane = tid & 31;
    const int wm = wid >> 2, wn = wid & 3;   // 2 x 4
    const int g = lane >> 2, t = lane & 3;
    const int l8 = lane & 15;

    float c[4][4][4];
    #pragma unroll
    for (int mt = 0; mt < 4; mt++)
        #pragma unroll
        for (int nt = 0; nt < 4; nt++)
            #pragma unroll
            for (int e = 0; e < 4; e++) c[mt][nt][e] = 0.f;

    // prefetch regs
    float4 ra[4], rw[4];
    {
        #pragma unroll
        for (int i = 0; i < 4; i++) {
            int idx = i * 256 + tid;
            int r = idx >> 3, cw = (idx & 7) * 2;        // word col
            ra[i] = *(const float4*)(A + (size_t)(m0 + r) * Dn + cw * 2);
            rw[i] = *(const float4*)(W + (size_t)(n0 + r) * Dn + cw * 2);
        }
    }

    for (int k0 = 0; k0 < Dn; k0 += 32) {
        // store staged regs -> smem (split hi/lo)
        #pragma unroll
        for (int i = 0; i < 4; i++) {
            int idx = i * 256 + tid;
            int r = idx >> 3, cw = (idx & 7) * 2;
            unsigned h0, l0, h1, l1;
            split_pack(ra[i].x, ra[i].y, h0, l0);
            split_pack(ra[i].z, ra[i].w, h1, l1);
            sAhi[r * GSTW + cw] = h0; sAhi[r * GSTW + cw + 1] = h1;
            sAlo[r * GSTW + cw] = l0; sAlo[r * GSTW + cw + 1] = l1;
            split_pack(rw[i].x, rw[i].y, h0, l0);
            split_pack(rw[i].z, rw[i].w, h1, l1);
            sWhi[r * GSTW + cw] = h0; sWhi[r * GSTW + cw + 1] = h1;
            sWlo[r * GSTW + cw] = l0; sWlo[r * GSTW + cw + 1] = l1;
        }
        __syncthreads();

        // prefetch next tile while mma runs
        if (k0 + 32 < Dn) {
            #pragma unroll
            for (int i = 0; i < 4; i++) {
                int idx = i * 256 + tid;
                int r = idx >> 3, cw = (idx & 7) * 2;
                ra[i] = *(const float4*)(A + (size_t)(m0 + r) * Dn + k0 + 32 + cw * 2);
                rw[i] = *(const float4*)(W + (size_t)(n0 + r) * Dn + k0 + 32 + cw * 2);
            }
        }

        #pragma unroll
        for (int kt = 0; kt < 2; kt++) {
            unsigned ah[4][4], al[4][4], bh[4][2], bl[4][2];
            const int sub = lane >> 3;
            #pragma unroll
            for (int mt = 0; mt < 4; mt++) {
                int r = wm * 64 + mt * 16 + (lane & 7) + (sub & 1) * 8;
                int kw = kt * 8 + (sub >> 1) * 4;
                ldsm4(ah[mt], smem_u32(&sAhi[r * GSTW + kw]));
                ldsm4(al[mt], smem_u32(&sAlo[r * GSTW + kw]));
            }
            #pragma unroll
            for (int nt = 0; nt < 4; nt++) {
                int r = wn * 32 + nt * 8 + (l8 & 7);
                int kw = kt * 8 + (l8 >> 3) * 4;
                ldsm2(bh[nt], smem_u32(&sWhi[r * GSTW + kw]));
                ldsm2(bl[nt], smem_u32(&sWlo[r * GSTW + kw]));
            }
            #pragma unroll
            for (int mt = 0; mt < 4; mt++)
                #pragma unroll
                for (int nt = 0; nt < 4; nt++) {
                    mma16816(c[mt][nt], ah[mt], bh[nt]);
                    mma16816(c[mt][nt], ah[mt], bl[nt]);
                    mma16816(c[mt][nt], al[mt], bh[nt]);
                }
        }
        __syncthreads();
    }

    // epilogue
    #pragma unroll
    for (int mt = 0; mt < 4; mt++) {
        #pragma unroll
        for (int nt = 0; nt < 4; nt++) {
            const int row = m0 + wm * 64 + mt * 16 + g;
            const int col = n0 + wn * 32 + nt * 8 + 2 * t;
            const float b0 = bias[col], b1 = bias[col + 1];
            #pragma unroll
            for (int half = 0; half < 2; half++) {
                const int r = row + half * 8;
                const float v0 = (c[mt][nt][half * 2 + 0] + b0) * scale;
                const float v1 = (c[mt][nt][half * 2 + 1] + b1) * scale;
                const int bb = r >> 10, s = r & 1023;
                float2 val = make_float2(v0, v1);
                if (mode == 2) {
                    *(float2*)(C + (size_t)r * Dn + col) = val;
                } else {
                    const int h = col >> 6, d = col & 63;
                    *(float2*)(C + (((size_t)(bb * Hn + h) * Sn + s) * DHn) + d) = val;
                }
            }
        }
    }
}

// ---------------------------------------------------------------------------
// Tensor-core flash attention (split-bf16 3x).
// Grid (S/64, H, B), 128 threads (4 warps), warp owns 16 q-rows.
// Key tile = 64. K staged [key][dh] (hi/lo), V staged transposed [dh][seq].
// P reuses S c-frags directly as A-frags. Mask -> -inf; graph fused (h==15).
// ---------------------------------------------------------------------------
#define ASTW 36   // words per smem row (64 bf16 data + 8 bf16 pad)

__global__ __launch_bounds__(128)
void attn_mma(const float* __restrict__ q, const float* __restrict__ k,
              const float* __restrict__ v, const int* __restrict__ mask,
              const float* __restrict__ graph, float* __restrict__ ctx)
{
    extern __shared__ __align__(16) unsigned char dynsmem[];
    unsigned* Kshi = (unsigned*)dynsmem;                 // 64*36 words
    unsigned* Kslo = Kshi + 64 * ASTW;
    unsigned* Vthi = Kslo + 64 * ASTW;                   // transposed V [dh][seq]
    unsigned* Vtlo = Vthi + 64 * ASTW;
    float* Gs = (float*)(Vtlo + 64 * ASTW);              // 64*68 floats
    unsigned char* Ms = (unsigned char*)(Gs + 64 * 68);  // 64*80 bytes

    const int tid = threadIdx.x;
    const int w = tid >> 5, lane = tid & 31;
    const int g = lane >> 2, t = lane & 3;
    const int l8 = lane & 15;
    const int h = blockIdx.y, b = blockIdx.z;
    const int q0 = blockIdx.x * 64;
    const bool lastH = (h == Hn - 1);

    const float* kbase = k + (size_t)((b * Hn + h) * Sn) * DHn;
    const float* vbase = v + (size_t)((b * Hn + h) * Sn) * DHn;
    const int* mbase = mask + (size_t)(b * Sn) * Sn;
    const float* gbase = graph + (size_t)(b * Sn) * Sn;

    // Q fragments: gmem -> regs once (hi/lo), rows w*16 + g (+8)
    unsigned qh[4][4], ql[4][4];
    {
        const float* qb = q + ((size_t)((b * Hn + h) * Sn) + q0 + w * 16) * DHn;
        #pragma unroll
        for (int kt = 0; kt < 4; kt++) {
            float2 v0 = *(const float2*)(qb + (size_t)g * DHn + kt * 16 + 2 * t);
            float2 v1 = *(const float2*)(qb + (size_t)(g + 8) * DHn + kt * 16 + 2 * t);
            float2 v2 = *(const float2*)(qb + (size_t)g * DHn + kt * 16 + 2 * t + 8);
            float2 v3 = *(const float2*)(qb + (size_t)(g + 8) * DHn + kt * 16 + 2 * t + 8);
            split_pack(v0.x, v0.y, qh[kt][0], ql[kt][0]);
            split_pack(v1.x, v1.y, qh[kt][1], ql[kt][1]);
            split_pack(v2.x, v2.y, qh[kt][2], ql[kt][2]);
            split_pack(v3.x, v3.y, qh[kt][3], ql[kt][3]);
        }
    }

    float O[8][4];
    #pragma unroll
    for (int nt = 0; nt < 8; nt++)
        #pragma unroll
        for (int e = 0; e < 4; e++) O[nt][e] = 0.f;
    float mA = -1e30f, mB = -1e30f, lA = 0.f, lB = 0.f;

    for (int kt0 = 0; kt0 < Sn; kt0 += 64) {
        __syncthreads();
        // --- stage K (hi/lo) ---
        #pragma unroll
        for (int i = 0; i < 8; i++) {
            int idx = i * 128 + tid;
            int r = idx >> 4, cw = (idx & 15) * 2;
            float4 kv = *(const float4*)(kbase + (size_t)(kt0 + r) * DHn + cw * 2);
            unsigned h0, l0, h1, l1;
            split_pack(kv.x, kv.y, h0, l0);
            split_pack(kv.z, kv.w, h1, l1);
            Kshi[r * ASTW + cw] = h0; Kshi[r * ASTW + cw + 1] = h1;
            Kslo[r * ASTW + cw] = l0; Kslo[r * ASTW + cw + 1] = l1;
        }
        // --- stage V transposed: Vt[dh][seq] ---
        #pragma unroll
        for (int i = 0; i < 8; i++) {
            int idx = i * 128 + tid;
            int d = idx & 63, sg = idx >> 6;       // sg in 0..15 (4 seq each)
            const float* vp = vbase + (size_t)(kt0 + sg * 4) * DHn + d;
            float v0 = vp[0], v1 = vp[DHn], v2 = vp[2 * DHn], v3 = vp[3 * DHn];
            unsigned h0, l0, h1, l1;
            split_pack(v0, v1, h0, l0);
            split_pack(v2, v3, h1, l1);
            Vthi[d * ASTW + sg * 2] = h0; Vthi[d * ASTW + sg * 2 + 1] = h1;
            Vtlo[d * ASTW + sg * 2] = l0; Vtlo[d * ASTW + sg * 2 + 1] = l1;
        }
        // --- stage mask (int32 -> bytes) ---
        #pragma unroll
        for (int i = 0; i < 8; i++) {
            int idx = i * 128 + tid;
            int r = idx >> 4, cc = (idx & 15) * 4;
            int4 mv = *(const int4*)(mbase + (size_t)(q0 + r) * Sn + kt0 + cc);
            uchar4 pk;
            pk.x = (unsigned char)(mv.x != 0);
            pk.y = (unsigned char)(mv.y != 0);
            pk.z = (unsigned char)(mv.z != 0);
            pk.w = (unsigned char)(mv.w != 0);
            *(uchar4*)&Ms[r * 80 + cc] = pk;
        }
        // --- stage graph (last head only) ---
        if (lastH) {
            #pragma unroll
            for (int i = 0; i < 8; i++) {
                int idx = i * 128 + tid;
                int r = idx >> 4, cc = (idx & 15) * 4;
                float4 gv = *(const float4*)(gbase + (size_t)(q0 + r) * Sn + kt0 + cc);
                *(float4*)&Gs[r * 68 + cc] = gv;
            }
        }
        __syncthreads();

        // --- S = Q K^T (3x split) ---
        float S[8][4];
        #pragma unroll
        for (int nt = 0; nt < 8; nt++) {
            #pragma unroll
            for (int e = 0; e < 4; e++) S[nt][e] = 0.f;
            #pragma unroll
            for (int kt = 0; kt < 4; kt++) {
                unsigned kh[2], kl[2];
                int r = nt * 8 + (l8 & 7);
                int kw = kt * 8 + (l8 >> 3) * 4;
                ldsm2(kh, smem_u32(&Kshi[r * ASTW + kw]));
                ldsm2(kl, smem_u32(&Kslo[r * ASTW + kw]));
                mma16816(S[nt], qh[kt], kh);
                mma16816(S[nt], qh[kt], kl);
                mma16816(S[nt], ql[kt], kh);
            }
        }

        // --- mask, online softmax ---
        const int rA = w * 16 + g, rB = rA + 8;
        float tmA = -CUDART_INF_F, tmB = -CUDART_INF_F;
        #pragma unroll
        for (int nt = 0; nt < 8; nt++) {
            const int col = nt * 8 + 2 * t;
            if (Ms[rA * 80 + col])     S[nt][0] = -CUDART_INF_F;
            if (Ms[rA * 80 + col + 1]) S[nt][1] = -CUDART_INF_F;
            if (Ms[rB * 80 + col])     S[nt][2] = -CUDART_INF_F;
            if (Ms[rB * 80 + col + 1]) S[nt][3] = -CUDART_INF_F;
            tmA = fmaxf(tmA, fmaxf(S[nt][0], S[nt][1]));
            tmB = fmaxf(tmB, fmaxf(S[nt][2], S[nt][3]));
        }
        tmA = fmaxf(tmA, __shfl_xor_sync(0xffffffff, tmA, 1));
        tmA = fmaxf(tmA, __shfl_xor_sync(0xffffffff, tmA, 2));
        tmB = fmaxf(tmB, __shfl_xor_sync(0xffffffff, tmB, 1));
        tmB = fmaxf(tmB, __shfl_xor_sync(0xffffffff, tmB, 2));

        const float mAn = fmaxf(mA, tmA), mBn = fmaxf(mB, tmB);
        const float fA = __expf(mA - mAn), fB = __expf(mB - mBn);
        mA = mAn; mB = mBn;
        lA *= fA; lB *= fB;
        #pragma unroll
        for (int nt = 0; nt < 8; nt++) {
            O[nt][0] *= fA; O[nt][1] *= fA;
            O[nt][2] *= fB; O[nt][3] *= fB;
        }

        float rsA = 0.f, rsB = 0.f;
        #pragma unroll
        for (int nt = 0; nt < 8; nt++) {
            float p0 = __expf(S[nt][0] - mA);
            float p1 = __expf(S[nt][1] - mA);
            float p2 = __expf(S[nt][2] - mB);
            float p3 = __expf(S[nt][3] - mB);
            if (lastH) {
                const int col = nt * 8 + 2 * t;
                p0 *= Gs[rA * 68 + col];
                p1 *= Gs[rA * 68 + col + 1];
                p2 *= Gs[rB * 68 + col];
                p3 *= Gs[rB * 68 + col + 1];
            }
            S[nt][0] = p0; S[nt][1] = p1; S[nt][2] = p2; S[nt][3] = p3;
            rsA += p0 + p1; rsB += p2 + p3;
        }
        rsA += __shfl_xor_sync(0xffffffff, rsA, 1);
        rsA += __shfl_xor_sync(0xffffffff, rsA, 2);
        rsB += __shfl_xor_sync(0xffffffff, rsB, 1);
        rsB += __shfl_xor_sync(0xffffffff, rsB, 2);
        lA += rsA; lB += rsB;

        // --- O += P V (3x split); P frags straight from S regs ---
        #pragma unroll
        for (int kt = 0; kt < 4; kt++) {
            unsigned ph[4], pl[4];
            split_pack(S[2 * kt][0],     S[2 * kt][1],     ph[0], pl[0]);
            split_pack(S[2 * kt][2],     S[2 * kt][3],     ph[1], pl[1]);
            split_pack(S[2 * kt + 1][0], S[2 * kt + 1][1], ph[2], pl[2]);
            split_pack(S[2 * kt + 1][2], S[2 * kt + 1][3], ph[3], pl[3]);
            #pragma unroll
            for (int nt = 0; nt < 8; nt++) {
                unsigned vh[2], vl[2];
                int r = nt * 8 + (l8 & 7);
                int kw = kt * 8 + (l8 >> 3) * 4;
                ldsm2(vh, smem_u32(&Vthi[r * ASTW + kw]));
                ldsm2(vl, smem_u32(&Vtlo[r * ASTW + kw]));
                mma16816(O[nt], ph, vh);
                mma16816(O[nt], ph, vl);
                mma16816(O[nt], pl, vh);
            }
        }
    }

    // epilogue: normalize + write [B,S,D]
    const float invA = 1.f / lA, invB = 1.f / lB;
    const int rowA = q0 + w * 16 + g, rowB = rowA + 8;
    #pragma unroll
    for (int nt = 0; nt < 8; nt++) {
        const int col = h * DHn + nt * 8 + 2 * t;
        *(float2*)(ctx + (size_t)(b * Sn + rowA) * Dn + col) =
            make_float2(O[nt][0] * invA, O[nt][1] * invA);
        *(float2*)(ctx + (size_t)(b * Sn + rowB) * Dn + col) =
            make_float2(O[nt][2] * invB, O[nt][3] * invB);
    }
}

// ---------------------------------------------------------------------------
// Launch
// ---------------------------------------------------------------------------
extern "C" void kernel_launch(void* const* d_in, const int* in_sizes, int n_in,
                              void* d_out, int out_size)
{
    const float* key   = (const float*)d_in[0];
    const float* value = (const float*)d_in[1];
    const float* query = (const float*)d_in[2];
    const int*   mask  = (const int*)d_in[3];
    const float* graph = (const float*)d_in[4];
    const float* Wq = (const float*)d_in[5];
    const float* bq = (const float*)d_in[6];
    const float* Wk = (const float*)d_in[7];
    const float* bk = (const float*)d_in[8];
    const float* Wv = (const float*)d_in[9];
    const float* bv = (const float*)d_in[10];
    const float* Wo = (const float*)d_in[11];
    const float* bo = (const float*)d_in[12];
    float* out = (float*)d_out;

    void *qp, *kp, *vp, *cp;
    cudaGetSymbolAddress(&qp, g_q);
    cudaGetSymbolAddress(&kp, g_k);
    cudaGetSymbolAddress(&vp, g_v);
    cudaGetSymbolAddress(&cp, g_ctx);

    static int smem_set = 0;
    if (!smem_set) {
        cudaFuncSetAttribute(attn_mma, cudaFuncAttributeMaxDynamicSharedMemorySize, 65536);
        smem_set = 1;
    }
    const int attn_smem = 4 * 64 * ASTW * 4 + 64 * 68 * 4 + 64 * 80;  // ~59.4KB

    dim3 ggrid(Dn / 128, Mn / 128);   // (8, 64)
    gemm_bf16x3<<<ggrid, 256>>>(query, Wq, bq, (float*)qp, 0, 0.125f);
    gemm_bf16x3<<<ggrid, 256>>>(key,   Wk, bk, (float*)kp, 0, 1.0f);
    gemm_bf16x3<<<ggrid, 256>>>(value, Wv, bv, (float*)vp, 0, 1.0f);

    attn_mma<<<dim3(Sn / 64, Hn, Bn), 128, attn_smem>>>(
        (const float*)qp, (const float*)kp, (const float*)vp,
        mask, graph, (float*)cp);

    gemm_bf16x3<<<ggrid, 256>>>((const float*)cp, Wo, bo, out, 2, 1.0f);
}

// round 5
// speedup vs baseline: 3.3453x; 1.1757x over previous
#include <cuda_runtime.h>
#include <cuda_bf16.h>
#include <math_constants.h>

#define Bn  8
#define Sn  1024
#define Dn  1024
#define Hn  16
#define DHn 64
#define Mn  (Bn * Sn)   // 8192

// ---------------------------------------------------------------------------
// Device-global scratch (bf16 hi/lo pairs)
// ---------------------------------------------------------------------------
__device__ __nv_bfloat16 gin_qh[Mn * Dn], gin_ql[Mn * Dn];
__device__ __nv_bfloat16 gin_kh[Mn * Dn], gin_kl[Mn * Dn];
__device__ __nv_bfloat16 gin_vh[Mn * Dn], gin_vl[Mn * Dn];
__device__ __nv_bfloat16 gWqh[Dn * Dn], gWql[Dn * Dn];
__device__ __nv_bfloat16 gWkh[Dn * Dn], gWkl[Dn * Dn];
__device__ __nv_bfloat16 gWvh[Dn * Dn], gWvl[Dn * Dn];
__device__ __nv_bfloat16 gWoh[Dn * Dn], gWol[Dn * Dn];
__device__ __nv_bfloat16 g_qh[Mn * Dn], g_ql[Mn * Dn];   // [B,H,S,DH]
__device__ __nv_bfloat16 g_kh[Mn * Dn], g_kl[Mn * Dn];
__device__ __nv_bfloat16 g_vh[Mn * Dn], g_vl[Mn * Dn];
__device__ __nv_bfloat16 g_ctxh[Mn * Dn], g_ctxl[Mn * Dn]; // [B,S,D]

// ---------------------------------------------------------------------------
// helpers
// ---------------------------------------------------------------------------
__device__ __forceinline__ unsigned smem_u32(const void* p) {
    return (unsigned)__cvta_generic_to_shared(p);
}
__device__ __forceinline__ void mma16816(float* c, const unsigned* a, const unsigned* b) {
    asm volatile(
        "mma.sync.aligned.m16n8k16.row.col.f32.bf16.bf16.f32 "
        "{%0,%1,%2,%3},{%4,%5,%6,%7},{%8,%9},{%0,%1,%2,%3};\n"
        : "+f"(c[0]), "+f"(c[1]), "+f"(c[2]), "+f"(c[3])
        : "r"(a[0]), "r"(a[1]), "r"(a[2]), "r"(a[3]), "r"(b[0]), "r"(b[1]));
}
__device__ __forceinline__ void ldsm4(unsigned* r, unsigned addr) {
    asm volatile("ldmatrix.sync.aligned.m8n8.x4.shared.b16 {%0,%1,%2,%3},[%4];\n"
                 : "=r"(r[0]), "=r"(r[1]), "=r"(r[2]), "=r"(r[3]) : "r"(addr));
}
__device__ __forceinline__ void ldsm4t(unsigned* r, unsigned addr) {
    asm volatile("ldmatrix.sync.aligned.m8n8.x4.trans.shared.b16 {%0,%1,%2,%3},[%4];\n"
                 : "=r"(r[0]), "=r"(r[1]), "=r"(r[2]), "=r"(r[3]) : "r"(addr));
}
__device__ __forceinline__ void split_pack(float x, float y, unsigned& hi, unsigned& lo) {
    __nv_bfloat16 hx = __float2bfloat16(x);
    __nv_bfloat16 hy = __float2bfloat16(y);
    float rx = x - __bfloat162float(hx);
    float ry = y - __bfloat162float(hy);
    __nv_bfloat162 h; h.x = hx; h.y = hy;
    __nv_bfloat162 l; l.x = __float2bfloat16(rx); l.y = __float2bfloat16(ry);
    hi = *(unsigned*)&h;
    lo = *(unsigned*)&l;
}
// fast 2^y, FMA-only (no MUFU). |rel err| < 3e-6 on clamped range.
__device__ __forceinline__ float exp2p(float y) {
    y = fmaxf(fminf(y, 60.f), -60.f);
    float z = y + 12582912.f;              // 1.5*2^23
    int i = __float_as_int(z) << 23;
    float f = y - (z - 12582912.f);
    float p = 1.3333558e-3f;
    p = fmaf(p, f, 9.6181291e-3f);
    p = fmaf(p, f, 5.5504109e-2f);
    p = fmaf(p, f, 2.4022651e-1f);
    p = fmaf(p, f, 6.9314718e-1f);
    p = fmaf(p, f, 1.0f);
    return __int_as_float(__float_as_int(p) + i);
}
#define CPA16(smem, gmem) asm volatile("cp.async.cg.shared.global [%0], [%1], 16;\n" :: "r"(smem), "l"(gmem))
#define CPA_COMMIT()      asm volatile("cp.async.commit_group;\n")
#define CPA_WAIT0()       asm volatile("cp.async.wait_group 0;\n" ::: "memory")

// ---------------------------------------------------------------------------
// Pre-split: fp32 -> bf16 hi/lo
// ---------------------------------------------------------------------------
__global__ void split_fp32(const float* __restrict__ src,
                           __nv_bfloat16* __restrict__ hi,
                           __nv_bfloat16* __restrict__ lo, int n2)
{
    int i = blockIdx.x * blockDim.x + threadIdx.x;
    if (i < n2) {
        float2 v = ((const float2*)src)[i];
        unsigned h, l;
        split_pack(v.x, v.y, h, l);
        ((unsigned*)hi)[i] = h;
        ((unsigned*)lo)[i] = l;
    }
}

// ---------------------------------------------------------------------------
// Split-bf16 (3x) GEMM, cp.async double-buffered.
// C = A[M,K] @ W[N,K]^T + bias.  Inputs pre-split bf16 hi/lo.
// Block 128x128, BK=32, 256 threads (2x4 warps, warp tile 64x32).
// mode 0: write head-split bf16 hi/lo [B,H,S,DH], scaled.
// mode 2: write plain fp32 [M,N].
// ---------------------------------------------------------------------------
#define GST 80  // bytes per smem row (64B data + 16B pad)

__global__ __launch_bounds__(256)
void gemm_bf16x3(const __nv_bfloat16* __restrict__ Ahi, const __nv_bfloat16* __restrict__ Alo,
                 const __nv_bfloat16* __restrict__ Whi, const __nv_bfloat16* __restrict__ Wlo,
                 const float* __restrict__ bias,
                 float* __restrict__ Cf,
                 __nv_bfloat16* __restrict__ Ch, __nv_bfloat16* __restrict__ Cl,
                 int mode, float scale)
{
    extern __shared__ __align__(16) char dsm[];
    const int tid = threadIdx.x;
    const int m0 = blockIdx.y * 128, n0 = blockIdx.x * 128;
    const int wid = tid >> 5, lane = tid & 31;
    const int wm = wid >> 2, wn = wid & 3;
    const int g = lane >> 2, t = lane & 3;
    const int sub = lane >> 3;

    float c[4][4][4];
    #pragma unroll
    for (int mt = 0; mt < 4; mt++)
        #pragma unroll
        for (int nt = 0; nt < 4; nt++)
            #pragma unroll
            for (int e = 0; e < 4; e++) c[mt][nt][e] = 0.f;

    auto issue = [&](int k0, int buf) {
        char* st = dsm + buf * 40960;
        #pragma unroll
        for (int i = 0; i < 2; i++) {
            int cc = i * 256 + tid;           // 0..511
            int r = cc >> 2, off = cc & 3;    // 4 x 16B per row
            size_t ga = (size_t)(m0 + r) * Dn + k0 + off * 8;
            size_t gw = (size_t)(n0 + r) * Dn + k0 + off * 8;
            unsigned sa = smem_u32(st + r * GST + off * 16);
            CPA16(sa,         Ahi + ga);
            CPA16(sa + 10240, Alo + ga);
            CPA16(sa + 20480, Whi + gw);
            CPA16(sa + 30720, Wlo + gw);
        }
    };

    issue(0, 0);
    CPA_COMMIT();

    for (int it = 0; it < Dn / 32; it++) {
        CPA_WAIT0();
        __syncthreads();
        if (it + 1 < Dn / 32) { issue((it + 1) * 32, (it + 1) & 1); CPA_COMMIT(); }

        char* st = dsm + (it & 1) * 40960;
        char* sAh = st; char* sAl = st + 10240;
        char* sWh = st + 20480; char* sWl = st + 30720;

        #pragma unroll
        for (int kt = 0; kt < 2; kt++) {
            unsigned ah[4][4], al[4][4], bh[4][2], bl[4][2];
            #pragma unroll
            for (int mt = 0; mt < 4; mt++) {
                int r = wm * 64 + mt * 16 + (lane & 7) + (sub & 1) * 8;
                int kb = kt * 32 + (sub >> 1) * 16;
                ldsm4(ah[mt], smem_u32(sAh + r * GST + kb));
                ldsm4(al[mt], smem_u32(sAl + r * GST + kb));
            }
            #pragma unroll
            for (int ntp = 0; ntp < 2; ntp++) {
                int r = wn * 32 + (ntp * 2 + (sub >> 1)) * 8 + (lane & 7);
                int kb = kt * 32 + (sub & 1) * 16;
                unsigned tmp[4];
                ldsm4(tmp, smem_u32(sWh + r * GST + kb));
                bh[2 * ntp][0] = tmp[0]; bh[2 * ntp][1] = tmp[1];
                bh[2 * ntp + 1][0] = tmp[2]; bh[2 * ntp + 1][1] = tmp[3];
                ldsm4(tmp, smem_u32(sWl + r * GST + kb));
                bl[2 * ntp][0] = tmp[0]; bl[2 * ntp][1] = tmp[1];
                bl[2 * ntp + 1][0] = tmp[2]; bl[2 * ntp + 1][1] = tmp[3];
            }
            #pragma unroll
            for (int mt = 0; mt < 4; mt++)
                #pragma unroll
                for (int nt = 0; nt < 4; nt++) {
                    mma16816(c[mt][nt], ah[mt], bh[nt]);
                    mma16816(c[mt][nt], ah[mt], bl[nt]);
                    mma16816(c[mt][nt], al[mt], bh[nt]);
                }
        }
    }

    // epilogue
    #pragma unroll
    for (int mt = 0; mt < 4; mt++) {
        #pragma unroll
        for (int nt = 0; nt < 4; nt++) {
            const int row = m0 + wm * 64 + mt * 16 + g;
            const int col = n0 + wn * 32 + nt * 8 + 2 * t;
            const float b0 = bias[col], b1 = bias[col + 1];
            #pragma unroll
            for (int half = 0; half < 2; half++) {
                const int r = row + half * 8;
                const float v0 = (c[mt][nt][half * 2 + 0] + b0) * scale;
                const float v1 = (c[mt][nt][half * 2 + 1] + b1) * scale;
                if (mode == 2) {
                    *(float2*)(Cf + (size_t)r * Dn + col) = make_float2(v0, v1);
                } else {
                    const int bb = r >> 10, s = r & 1023;
                    const int hh = col >> 6, d = col & 63;
                    size_t idx = (((size_t)(bb * Hn + hh) * Sn + s) * DHn) + d;
                    unsigned hw, lw;
                    split_pack(v0, v1, hw, lw);
                    *(unsigned*)(Ch + idx) = hw;
                    *(unsigned*)(Cl + idx) = lw;
                }
            }
        }
    }
}

// ---------------------------------------------------------------------------
// Tensor-core flash attention, MUFU-free softmax (scores in log2 units).
// Grid (S/64, H, B), 128 threads (4 warps), warp owns 16 q-rows, key tile 64.
// No max subtraction (scores bounded); p = 2^s via FMA poly; mask -> p=0.
// V consumed via ldmatrix.trans.  Writes ctx as bf16 hi/lo [B,S,D].
// ---------------------------------------------------------------------------
#define AST 144  // bytes per smem row (128B data + 16B pad)

__global__ __launch_bounds__(128)
void attn_mma(const __nv_bfloat16* __restrict__ qh_g, const __nv_bfloat16* __restrict__ ql_g,
              const __nv_bfloat16* __restrict__ kh_g, const __nv_bfloat16* __restrict__ kl_g,
              const __nv_bfloat16* __restrict__ vh_g, const __nv_bfloat16* __restrict__ vl_g,
              const int* __restrict__ mask, const float* __restrict__ graph,
              __nv_bfloat16* __restrict__ ctxh, __nv_bfloat16* __restrict__ ctxl)
{
    __shared__ __align__(16) char sKh[64 * AST];
    __shared__ __align__(16) char sKl[64 * AST];
    __shared__ __align__(16) char sVh[64 * AST];
    __shared__ __align__(16) char sVl[64 * AST];
    __shared__ unsigned char Ms[64 * 80];

    const int tid = threadIdx.x;
    const int w = tid >> 5, lane = tid & 31;
    const int g = lane >> 2, t = lane & 3;
    const int sub = lane >> 3;
    const int hh = blockIdx.y, b = blockIdx.z;
    const int q0 = blockIdx.x * 64;
    const bool lastH = (hh == Hn - 1);

    const size_t hoff = (size_t)((b * Hn + hh) * Sn) * DHn;
    const int* mbase = mask + (size_t)(b * Sn) * Sn;
    const float* gbase = graph + (size_t)(b * Sn) * Sn;

    // Q fragments (hi/lo) from gmem, once
    unsigned qh[4][4], ql[4][4];
    {
        const __nv_bfloat16* qb_h = qh_g + hoff + (size_t)(q0 + w * 16) * DHn;
        const __nv_bfloat16* qb_l = ql_g + hoff + (size_t)(q0 + w * 16) * DHn;
        #pragma unroll
        for (int kt = 0; kt < 4; kt++) {
            int c0 = kt * 16 + 2 * t;
            qh[kt][0] = *(const unsigned*)(qb_h + (size_t)g * DHn + c0);
            qh[kt][1] = *(const unsigned*)(qb_h + (size_t)(g + 8) * DHn + c0);
            qh[kt][2] = *(const unsigned*)(qb_h + (size_t)g * DHn + c0 + 8);
            qh[kt][3] = *(const unsigned*)(qb_h + (size_t)(g + 8) * DHn + c0 + 8);
            ql[kt][0] = *(const unsigned*)(qb_l + (size_t)g * DHn + c0);
            ql[kt][1] = *(const unsigned*)(qb_l + (size_t)(g + 8) * DHn + c0);
            ql[kt][2] = *(const unsigned*)(qb_l + (size_t)g * DHn + c0 + 8);
            ql[kt][3] = *(const unsigned*)(qb_l + (size_t)(g + 8) * DHn + c0 + 8);
        }
    }

    float O[8][4];
    #pragma unroll
    for (int nt = 0; nt < 8; nt++)
        #pragma unroll
        for (int e = 0; e < 4; e++) O[nt][e] = 0.f;
    float lA = 0.f, lB = 0.f;
    const int rA = w * 16 + g, rB = rA + 8;

    for (int kt0 = 0; kt0 < Sn; kt0 += 64) {
        __syncthreads();   // all warps done reading previous tile
        // stage K/V hi/lo via cp.async (raw bf16 rows)
        #pragma unroll
        for (int i = 0; i < 4; i++) {
            int cc = i * 128 + tid;          // 0..511
            int r = cc >> 3, off = cc & 7;   // 8 x 16B per row
            size_t gsrc = hoff + (size_t)(kt0 + r) * DHn + off * 8;
            CPA16(smem_u32(sKh + r * AST + off * 16), kh_g + gsrc);
            CPA16(smem_u32(sKl + r * AST + off * 16), kl_g + gsrc);
            CPA16(smem_u32(sVh + r * AST + off * 16), vh_g + gsrc);
            CPA16(smem_u32(sVl + r * AST + off * 16), vl_g + gsrc);
        }
        CPA_COMMIT();
        // stage mask (int32 -> bytes)
        #pragma unroll
        for (int i = 0; i < 8; i++) {
            int idx = i * 128 + tid;
            int r = idx >> 4, cc = (idx & 15) * 4;
            int4 mv = *(const int4*)(mbase + (size_t)(q0 + r) * Sn + kt0 + cc);
            uchar4 pk;
            pk.x = (unsigned char)(mv.x != 0);
            pk.y = (unsigned char)(mv.y != 0);
            pk.z = (unsigned char)(mv.z != 0);
            pk.w = (unsigned char)(mv.w != 0);
            *(uchar4*)&Ms[r * 80 + cc] = pk;
        }
        CPA_WAIT0();
        __syncthreads();

        // S = Q K^T (3x split), scores in log2 units
        float S[8][4];
        #pragma unroll
        for (int nt = 0; nt < 8; nt++)
            #pragma unroll
            for (int e = 0; e < 4; e++) S[nt][e] = 0.f;
        #pragma unroll
        for (int kt = 0; kt < 4; kt++) {
            #pragma unroll
            for (int ntp = 0; ntp < 4; ntp++) {
                int r = (ntp * 2 + (sub >> 1)) * 8 + (lane & 7);
                int kb = kt * 32 + (sub & 1) * 16;
                unsigned th[4], tl[4];
                ldsm4(th, smem_u32(sKh + r * AST + kb));
                ldsm4(tl, smem_u32(sKl + r * AST + kb));
                mma16816(S[2 * ntp],     qh[kt], th);
                mma16816(S[2 * ntp],     qh[kt], tl);
                mma16816(S[2 * ntp],     ql[kt], th);
                mma16816(S[2 * ntp + 1], qh[kt], th + 2);
                mma16816(S[2 * ntp + 1], qh[kt], tl + 2);
                mma16816(S[2 * ntp + 1], ql[kt], th + 2);
            }
        }

        // graph prefetch (last head only)
        float2 gA[8], gB[8];
        if (lastH) {
            #pragma unroll
            for (int nt = 0; nt < 8; nt++) {
                int col = kt0 + nt * 8 + 2 * t;
                gA[nt] = *(const float2*)(gbase + (size_t)(q0 + rA) * Sn + col);
                gB[nt] = *(const float2*)(gbase + (size_t)(q0 + rB) * Sn + col);
            }
        }

        // p = 2^s (FMA-only), mask -> 0, graph fused; accumulate l
        float la = 0.f, lb = 0.f;
        #pragma unroll
        for (int nt = 0; nt < 8; nt++) {
            const int col = nt * 8 + 2 * t;
            float p0 = exp2p(S[nt][0]);
            float p1 = exp2p(S[nt][1]);
            float p2 = exp2p(S[nt][2]);
            float p3 = exp2p(S[nt][3]);
            if (Ms[rA * 80 + col])     p0 = 0.f;
            if (Ms[rA * 80 + col + 1]) p1 = 0.f;
            if (Ms[rB * 80 + col])     p2 = 0.f;
            if (Ms[rB * 80 + col + 1]) p3 = 0.f;
            if (lastH) {
                p0 *= gA[nt].x; p1 *= gA[nt].y;
                p2 *= gB[nt].x; p3 *= gB[nt].y;
            }
            S[nt][0] = p0; S[nt][1] = p1; S[nt][2] = p2; S[nt][3] = p3;
            la += p0 + p1; lb += p2 + p3;
        }
        lA += la; lB += lb;

        // O += P V (3x split); V via ldmatrix.trans
        #pragma unroll
        for (int kt = 0; kt < 4; kt++) {
            unsigned ph[4], pl[4];
            split_pack(S[2 * kt][0],     S[2 * kt][1],     ph[0], pl[0]);
            split_pack(S[2 * kt][2],     S[2 * kt][3],     ph[1], pl[1]);
            split_pack(S[2 * kt + 1][0], S[2 * kt + 1][1], ph[2], pl[2]);
            split_pack(S[2 * kt + 1][2], S[2 * kt + 1][3], ph[3], pl[3]);
            #pragma unroll
            for (int ntp = 0; ntp < 4; ntp++) {
                int r = kt * 16 + (sub & 1) * 8 + (lane & 7);
                int cb = (2 * ntp + (sub >> 1)) * 16;
                unsigned th[4], tl[4];
                ldsm4t(th, smem_u32(sVh + r * AST + cb));
                ldsm4t(tl, smem_u32(sVl + r * AST + cb));
                mma16816(O[2 * ntp],     ph, th);
                mma16816(O[2 * ntp],     ph, tl);
                mma16816(O[2 * ntp],     pl, th);
                mma16816(O[2 * ntp + 1], ph, th + 2);
                mma16816(O[2 * ntp + 1], ph, tl + 2);
                mma16816(O[2 * ntp + 1], pl, th + 2);
            }
        }
    }

    // reduce l across the quad (cols split over t lanes)
    lA += __shfl_xor_sync(0xffffffff, lA, 1);
    lA += __shfl_xor_sync(0xffffffff, lA, 2);
    lB += __shfl_xor_sync(0xffffffff, lB, 1);
    lB += __shfl_xor_sync(0xffffffff, lB, 2);
    const float invA = 1.f / lA, invB = 1.f / lB;

    const int rowA = q0 + rA, rowB = q0 + rB;
    #pragma unroll
    for (int nt = 0; nt < 8; nt++) {
        const int col = hh * DHn + nt * 8 + 2 * t;
        unsigned hw, lw;
        split_pack(O[nt][0] * invA, O[nt][1] * invA, hw, lw);
        *(unsigned*)(ctxh + (size_t)(b * Sn + rowA) * Dn + col) = hw;
        *(unsigned*)(ctxl + (size_t)(b * Sn + rowA) * Dn + col) = lw;
        split_pack(O[nt][2] * invB, O[nt][3] * invB, hw, lw);
        *(unsigned*)(ctxh + (size_t)(b * Sn + rowB) * Dn + col) = hw;
        *(unsigned*)(ctxl + (size_t)(b * Sn + rowB) * Dn + col) = lw;
    }
}

// ---------------------------------------------------------------------------
// Launch
// ---------------------------------------------------------------------------
extern "C" void kernel_launch(void* const* d_in, const int* in_sizes, int n_in,
                              void* d_out, int out_size)
{
    const float* key   = (const float*)d_in[0];
    const float* value = (const float*)d_in[1];
    const float* query = (const float*)d_in[2];
    const int*   mask  = (const int*)d_in[3];
    const float* graph = (const float*)d_in[4];
    const float* Wq = (const float*)d_in[5];
    const float* bq = (const float*)d_in[6];
    const float* Wk = (const float*)d_in[7];
    const float* bk = (const float*)d_in[8];
    const float* Wv = (const float*)d_in[9];
    const float* bv = (const float*)d_in[10];
    const float* Wo = (const float*)d_in[11];
    const float* bo = (const float*)d_in[12];
    float* out = (float*)d_out;

    static int inited = 0;
    if (!inited) {
        cudaFuncSetAttribute(gemm_bf16x3, cudaFuncAttributeMaxDynamicSharedMemorySize, 81920);
        inited = 1;
    }

    #define SYM(p, s) void* p; cudaGetSymbolAddress(&p, s)
    SYM(iqh, gin_qh); SYM(iql, gin_ql);
    SYM(ikh, gin_kh); SYM(ikl, gin_kl);
    SYM(ivh, gin_vh); SYM(ivl, gin_vl);
    SYM(wqh, gWqh); SYM(wql, gWql);
    SYM(wkh, gWkh); SYM(wkl, gWkl);
    SYM(wvh, gWvh); SYM(wvl, gWvl);
    SYM(woh, gWoh); SYM(wol, gWol);
    SYM(pqh, g_qh); SYM(pql, g_ql);
    SYM(pkh, g_kh); SYM(pkl, g_kl);
    SYM(pvh, g_vh); SYM(pvl, g_vl);
    SYM(cxh, g_ctxh); SYM(cxl, g_ctxl);
    #undef SYM

    typedef __nv_bfloat16 bf;
    const int nIn = Mn * Dn / 2, nW = Dn * Dn / 2;
    split_fp32<<<(nIn + 255) / 256, 256>>>(query, (bf*)iqh, (bf*)iql, nIn);
    split_fp32<<<(nIn + 255) / 256, 256>>>(key,   (bf*)ikh, (bf*)ikl, nIn);
    split_fp32<<<(nIn + 255) / 256, 256>>>(value, (bf*)ivh, (bf*)ivl, nIn);
    split_fp32<<<(nW + 255) / 256, 256>>>(Wq, (bf*)wqh, (bf*)wql, nW);
    split_fp32<<<(nW + 255) / 256, 256>>>(Wk, (bf*)wkh, (bf*)wkl, nW);
    split_fp32<<<(nW + 255) / 256, 256>>>(Wv, (bf*)wvh, (bf*)wvl, nW);
    split_fp32<<<(nW + 255) / 256, 256>>>(Wo, (bf*)woh, (bf*)wol, nW);

    const float QSCALE = 0.125f * 1.4426950408889634f;   // fold log2e into Q
    dim3 ggrid(Dn / 128, Mn / 128);
    gemm_bf16x3<<<ggrid, 256, 81920>>>((bf*)iqh, (bf*)iql, (bf*)wqh, (bf*)wql, bq,
                                       nullptr, (bf*)pqh, (bf*)pql, 0, QSCALE);
    gemm_bf16x3<<<ggrid, 256, 81920>>>((bf*)ikh, (bf*)ikl, (bf*)wkh, (bf*)wkl, bk,
                                       nullptr, (bf*)pkh, (bf*)pkl, 0, 1.0f);
    gemm_bf16x3<<<ggrid, 256, 81920>>>((bf*)ivh, (bf*)ivl, (bf*)wvh, (bf*)wvl, bv,
                                       nullptr, (bf*)pvh, (bf*)pvl, 0, 1.0f);

    attn_mma<<<dim3(Sn / 64, Hn, Bn), 128>>>(
        (const bf*)pqh, (const bf*)pql, (const bf*)pkh, (const bf*)pkl,
        (const bf*)pvh, (const bf*)pvl, mask, graph, (bf*)cxh, (bf*)cxl);

    gemm_bf16x3<<<ggrid, 256, 81920>>>((const bf*)cxh, (const bf*)cxl,
                                       (bf*)woh, (bf*)wol, bo,
                                       out, nullptr, nullptr, 2, 1.0f);
}

// round 6
// speedup vs baseline: 3.5119x; 1.0498x over previous
#include <cuda_runtime.h>
#include <cuda_bf16.h>
#include <math_constants.h>

#define Bn  8
#define Sn  1024
#define Dn  1024
#define Hn  16
#define DHn 64
#define Mn  (Bn * Sn)   // 8192

// ---------------------------------------------------------------------------
// Device-global scratch
// ---------------------------------------------------------------------------
__device__ __nv_bfloat16 gin_qh[Mn * Dn], gin_ql[Mn * Dn];
__device__ __nv_bfloat16 gin_kh[Mn * Dn], gin_kl[Mn * Dn];
__device__ __nv_bfloat16 gin_vh[Mn * Dn], gin_vl[Mn * Dn];
__device__ __nv_bfloat16 gWqh[Dn * Dn], gWql[Dn * Dn];
__device__ __nv_bfloat16 gWkh[Dn * Dn], gWkl[Dn * Dn];
__device__ __nv_bfloat16 gWvh[Dn * Dn], gWvl[Dn * Dn];
__device__ __nv_bfloat16 gWoh[Dn * Dn], gWol[Dn * Dn];
__device__ __nv_bfloat16 g_qh[Mn * Dn], g_ql[Mn * Dn];   // [B,H,S,DH]
__device__ __nv_bfloat16 g_kh[Mn * Dn], g_kl[Mn * Dn];
__device__ __nv_bfloat16 g_vh[Mn * Dn], g_vl[Mn * Dn];
__device__ __nv_bfloat16 g_ctxh[Mn * Dn], g_ctxl[Mn * Dn]; // [B,S,D]
__device__ unsigned char g_mask[Bn * Sn * Sn];             // packed mask bytes

// ---------------------------------------------------------------------------
// helpers
// ---------------------------------------------------------------------------
__device__ __forceinline__ unsigned smem_u32(const void* p) {
    return (unsigned)__cvta_generic_to_shared(p);
}
__device__ __forceinline__ void mma16816(float* c, const unsigned* a, const unsigned* b) {
    asm volatile(
        "mma.sync.aligned.m16n8k16.row.col.f32.bf16.bf16.f32 "
        "{%0,%1,%2,%3},{%4,%5,%6,%7},{%8,%9},{%0,%1,%2,%3};\n"
        : "+f"(c[0]), "+f"(c[1]), "+f"(c[2]), "+f"(c[3])
        : "r"(a[0]), "r"(a[1]), "r"(a[2]), "r"(a[3]), "r"(b[0]), "r"(b[1]));
}
__device__ __forceinline__ void ldsm4(unsigned* r, unsigned addr) {
    asm volatile("ldmatrix.sync.aligned.m8n8.x4.shared.b16 {%0,%1,%2,%3},[%4];\n"
                 : "=r"(r[0]), "=r"(r[1]), "=r"(r[2]), "=r"(r[3]) : "r"(addr));
}
__device__ __forceinline__ void ldsm4t(unsigned* r, unsigned addr) {
    asm volatile("ldmatrix.sync.aligned.m8n8.x4.trans.shared.b16 {%0,%1,%2,%3},[%4];\n"
                 : "=r"(r[0]), "=r"(r[1]), "=r"(r[2]), "=r"(r[3]) : "r"(addr));
}
__device__ __forceinline__ void split_pack(float x, float y, unsigned& hi, unsigned& lo) {
    __nv_bfloat16 hx = __float2bfloat16(x);
    __nv_bfloat16 hy = __float2bfloat16(y);
    float rx = x - __bfloat162float(hx);
    float ry = y - __bfloat162float(hy);
    __nv_bfloat162 h; h.x = hx; h.y = hy;
    __nv_bfloat162 l; l.x = __float2bfloat16(rx); l.y = __float2bfloat16(ry);
    hi = *(unsigned*)&h;
    lo = *(unsigned*)&l;
}
// fast 2^y, FMA-only (no MUFU)
__device__ __forceinline__ float exp2p(float y) {
    y = fmaxf(fminf(y, 60.f), -60.f);
    float z = y + 12582912.f;              // 1.5*2^23
    int i = __float_as_int(z) << 23;
    float f = y - (z - 12582912.f);
    float p = 1.3333558e-3f;
    p = fmaf(p, f, 9.6181291e-3f);
    p = fmaf(p, f, 5.5504109e-2f);
    p = fmaf(p, f, 2.4022651e-1f);
    p = fmaf(p, f, 6.9314718e-1f);
    p = fmaf(p, f, 1.0f);
    return __int_as_float(__float_as_int(p) + i);
}
#define CPA16(smem, gmem) asm volatile("cp.async.cg.shared.global [%0], [%1], 16;\n" :: "r"(smem), "l"(gmem))
#define CPA_COMMIT()      asm volatile("cp.async.commit_group;\n")
#define CPA_WAIT0()       asm volatile("cp.async.wait_group 0;\n" ::: "memory")
#define CPA_WAIT1()       asm volatile("cp.async.wait_group 1;\n" ::: "memory")

// ---------------------------------------------------------------------------
// Pre-split kernels (fused: 3 inputs / 4 weights) + mask pack
// ---------------------------------------------------------------------------
__device__ __forceinline__ void do_split(const float* src, __nv_bfloat16* hi,
                                         __nv_bfloat16* lo, int i) {
    float2 v = ((const float2*)src)[i];
    unsigned h, l;
    split_pack(v.x, v.y, h, l);
    ((unsigned*)hi)[i] = h;
    ((unsigned*)lo)[i] = l;
}
__global__ void split_in3(const float* __restrict__ s0, const float* __restrict__ s1,
                          const float* __restrict__ s2,
                          __nv_bfloat16* h0, __nv_bfloat16* l0,
                          __nv_bfloat16* h1, __nv_bfloat16* l1,
                          __nv_bfloat16* h2, __nv_bfloat16* l2, int n2)
{
    int i = blockIdx.x * blockDim.x + threadIdx.x;
    if (i >= n2) return;
    switch (blockIdx.y) {
        case 0: do_split(s0, h0, l0, i); break;
        case 1: do_split(s1, h1, l1, i); break;
        default: do_split(s2, h2, l2, i); break;
    }
}
__global__ void split_in4(const float* __restrict__ s0, const float* __restrict__ s1,
                          const float* __restrict__ s2, const float* __restrict__ s3,
                          __nv_bfloat16* h0, __nv_bfloat16* l0,
                          __nv_bfloat16* h1, __nv_bfloat16* l1,
                          __nv_bfloat16* h2, __nv_bfloat16* l2,
                          __nv_bfloat16* h3, __nv_bfloat16* l3, int n2)
{
    int i = blockIdx.x * blockDim.x + threadIdx.x;
    if (i >= n2) return;
    switch (blockIdx.y) {
        case 0: do_split(s0, h0, l0, i); break;
        case 1: do_split(s1, h1, l1, i); break;
        case 2: do_split(s2, h2, l2, i); break;
        default: do_split(s3, h3, l3, i); break;
    }
}
__global__ void pack_mask(const int4* __restrict__ m, uchar4* __restrict__ o, int n4)
{
    int i = blockIdx.x * blockDim.x + threadIdx.x;
    if (i < n4) {
        int4 v = m[i];
        o[i] = make_uchar4((unsigned char)(v.x != 0), (unsigned char)(v.y != 0),
                           (unsigned char)(v.z != 0), (unsigned char)(v.w != 0));
    }
}

// ---------------------------------------------------------------------------
// Split-bf16 (3x) GEMM, cp.async double-buffered (unchanged from R5).
// ---------------------------------------------------------------------------
#define GST 80  // bytes per smem row (64B data + 16B pad)

__global__ __launch_bounds__(256)
void gemm_bf16x3(const __nv_bfloat16* __restrict__ Ahi, const __nv_bfloat16* __restrict__ Alo,
                 const __nv_bfloat16* __restrict__ Whi, const __nv_bfloat16* __restrict__ Wlo,
                 const float* __restrict__ bias,
                 float* __restrict__ Cf,
                 __nv_bfloat16* __restrict__ Ch, __nv_bfloat16* __restrict__ Cl,
                 int mode, float scale)
{
    extern __shared__ __align__(16) char dsm[];
    const int tid = threadIdx.x;
    const int m0 = blockIdx.y * 128, n0 = blockIdx.x * 128;
    const int wid = tid >> 5, lane = tid & 31;
    const int wm = wid >> 2, wn = wid & 3;
    const int g = lane >> 2, t = lane & 3;
    const int sub = lane >> 3;

    float c[4][4][4];
    #pragma unroll
    for (int mt = 0; mt < 4; mt++)
        #pragma unroll
        for (int nt = 0; nt < 4; nt++)
            #pragma unroll
            for (int e = 0; e < 4; e++) c[mt][nt][e] = 0.f;

    auto issue = [&](int k0, int buf) {
        char* st = dsm + buf * 40960;
        #pragma unroll
        for (int i = 0; i < 2; i++) {
            int cc = i * 256 + tid;
            int r = cc >> 2, off = cc & 3;
            size_t ga = (size_t)(m0 + r) * Dn + k0 + off * 8;
            size_t gw = (size_t)(n0 + r) * Dn + k0 + off * 8;
            unsigned sa = smem_u32(st + r * GST + off * 16);
            CPA16(sa,         Ahi + ga);
            CPA16(sa + 10240, Alo + ga);
            CPA16(sa + 20480, Whi + gw);
            CPA16(sa + 30720, Wlo + gw);
        }
    };

    issue(0, 0);
    CPA_COMMIT();

    for (int it = 0; it < Dn / 32; it++) {
        CPA_WAIT0();
        __syncthreads();
        if (it + 1 < Dn / 32) { issue((it + 1) * 32, (it + 1) & 1); CPA_COMMIT(); }

        char* st = dsm + (it & 1) * 40960;
        char* sAh = st; char* sAl = st + 10240;
        char* sWh = st + 20480; char* sWl = st + 30720;

        #pragma unroll
        for (int kt = 0; kt < 2; kt++) {
            unsigned ah[4][4], al[4][4], bh[4][2], bl[4][2];
            #pragma unroll
            for (int mt = 0; mt < 4; mt++) {
                int r = wm * 64 + mt * 16 + (lane & 7) + (sub & 1) * 8;
                int kb = kt * 32 + (sub >> 1) * 16;
                ldsm4(ah[mt], smem_u32(sAh + r * GST + kb));
                ldsm4(al[mt], smem_u32(sAl + r * GST + kb));
            }
            #pragma unroll
            for (int ntp = 0; ntp < 2; ntp++) {
                int r = wn * 32 + (ntp * 2 + (sub >> 1)) * 8 + (lane & 7);
                int kb = kt * 32 + (sub & 1) * 16;
                unsigned tmp[4];
                ldsm4(tmp, smem_u32(sWh + r * GST + kb));
                bh[2 * ntp][0] = tmp[0]; bh[2 * ntp][1] = tmp[1];
                bh[2 * ntp + 1][0] = tmp[2]; bh[2 * ntp + 1][1] = tmp[3];
                ldsm4(tmp, smem_u32(sWl + r * GST + kb));
                bl[2 * ntp][0] = tmp[0]; bl[2 * ntp][1] = tmp[1];
                bl[2 * ntp + 1][0] = tmp[2]; bl[2 * ntp + 1][1] = tmp[3];
            }
            #pragma unroll
            for (int mt = 0; mt < 4; mt++)
                #pragma unroll
                for (int nt = 0; nt < 4; nt++) {
                    mma16816(c[mt][nt], ah[mt], bh[nt]);
                    mma16816(c[mt][nt], ah[mt], bl[nt]);
                    mma16816(c[mt][nt], al[mt], bh[nt]);
                }
        }
    }

    #pragma unroll
    for (int mt = 0; mt < 4; mt++) {
        #pragma unroll
        for (int nt = 0; nt < 4; nt++) {
            const int row = m0 + wm * 64 + mt * 16 + g;
            const int col = n0 + wn * 32 + nt * 8 + 2 * t;
            const float b0 = bias[col], b1 = bias[col + 1];
            #pragma unroll
            for (int half = 0; half < 2; half++) {
                const int r = row + half * 8;
                const float v0 = (c[mt][nt][half * 2 + 0] + b0) * scale;
                const float v1 = (c[mt][nt][half * 2 + 1] + b1) * scale;
                if (mode == 2) {
                    *(float2*)(Cf + (size_t)r * Dn + col) = make_float2(v0, v1);
                } else {
                    const int bb = r >> 10, s = r & 1023;
                    const int hh = col >> 6, d = col & 63;
                    size_t idx = (((size_t)(bb * Hn + hh) * Sn + s) * DHn) + d;
                    unsigned hw, lw;
                    split_pack(v0, v1, hw, lw);
                    *(unsigned*)(Ch + idx) = hw;
                    *(unsigned*)(Cl + idx) = lw;
                }
            }
        }
    }
}

// ---------------------------------------------------------------------------
// Tensor-core flash attention, MUFU-free softmax, DOUBLE-BUFFERED K/V/mask.
// Grid (S/64, H, B), 128 threads (4 warps), warp owns 16 q-rows, key tile 64.
// Mask read from pre-packed byte array via cp.async.
// ---------------------------------------------------------------------------
#define AST 144                 // bytes per K/V smem row (128B data + 16B pad)
#define KVSTAGE (4 * 64 * AST)  // 36864 per stage (Kh,Kl,Vh,Vl)
#define MOFF (2 * KVSTAGE)      // mask stages start at 73728
#define MSTAGE (64 * 80)        // 5120 per stage
#define ATTN_SMEM (MOFF + 2 * MSTAGE)  // 83968

__global__ __launch_bounds__(128, 2)
void attn_mma(const __nv_bfloat16* __restrict__ qh_g, const __nv_bfloat16* __restrict__ ql_g,
              const __nv_bfloat16* __restrict__ kh_g, const __nv_bfloat16* __restrict__ kl_g,
              const __nv_bfloat16* __restrict__ vh_g, const __nv_bfloat16* __restrict__ vl_g,
              const unsigned char* __restrict__ maskp, const float* __restrict__ graph,
              __nv_bfloat16* __restrict__ ctxh, __nv_bfloat16* __restrict__ ctxl)
{
    extern __shared__ __align__(16) char dsm[];

    const int tid = threadIdx.x;
    const int w = tid >> 5, lane = tid & 31;
    const int g = lane >> 2, t = lane & 3;
    const int sub = lane >> 3;
    const int hh = blockIdx.y, b = blockIdx.z;
    const int q0 = blockIdx.x * 64;
    const bool lastH = (hh == Hn - 1);

    const size_t hoff = (size_t)((b * Hn + hh) * Sn) * DHn;
    const unsigned char* mbase = maskp + (size_t)(b * Sn) * Sn;
    const float* gbase = graph + (size_t)(b * Sn) * Sn;

    // Q fragments (hi/lo) from gmem, once
    unsigned qh[4][4], ql[4][4];
    {
        const __nv_bfloat16* qb_h = qh_g + hoff + (size_t)(q0 + w * 16) * DHn;
        const __nv_bfloat16* qb_l = ql_g + hoff + (size_t)(q0 + w * 16) * DHn;
        #pragma unroll
        for (int kt = 0; kt < 4; kt++) {
            int c0 = kt * 16 + 2 * t;
            qh[kt][0] = *(const unsigned*)(qb_h + (size_t)g * DHn + c0);
            qh[kt][1] = *(const unsigned*)(qb_h + (size_t)(g + 8) * DHn + c0);
            qh[kt][2] = *(const unsigned*)(qb_h + (size_t)g * DHn + c0 + 8);
            qh[kt][3] = *(const unsigned*)(qb_h + (size_t)(g + 8) * DHn + c0 + 8);
            ql[kt][0] = *(const unsigned*)(qb_l + (size_t)g * DHn + c0);
            ql[kt][1] = *(const unsigned*)(qb_l + (size_t)(g + 8) * DHn + c0);
            ql[kt][2] = *(const unsigned*)(qb_l + (size_t)g * DHn + c0 + 8);
            ql[kt][3] = *(const unsigned*)(qb_l + (size_t)(g + 8) * DHn + c0 + 8);
        }
    }

    float O[8][4];
    #pragma unroll
    for (int nt = 0; nt < 8; nt++)
        #pragma unroll
        for (int e = 0; e < 4; e++) O[nt][e] = 0.f;
    float lA = 0.f, lB = 0.f;
    const int rA = w * 16 + g, rB = rA + 8;

    // stage K/V (4 x 16B per thread) + mask (2 x 16B per thread) for tile index kt16
    auto issue = [&](int kt16) {
        const int buf = kt16 & 1;
        char* st = dsm + buf * KVSTAGE;
        const int kt0 = kt16 * 64;
        #pragma unroll
        for (int i = 0; i < 4; i++) {
            int cc = i * 128 + tid;
            int r = cc >> 3, off = cc & 7;
            size_t gsrc = hoff + (size_t)(kt0 + r) * DHn + off * 8;
            CPA16(smem_u32(st + r * AST + off * 16),                kh_g + gsrc);
            CPA16(smem_u32(st + 64 * AST + r * AST + off * 16),     kl_g + gsrc);
            CPA16(smem_u32(st + 2 * 64 * AST + r * AST + off * 16), vh_g + gsrc);
            CPA16(smem_u32(st + 3 * 64 * AST + r * AST + off * 16), vl_g + gsrc);
        }
        char* ms = dsm + MOFF + buf * MSTAGE;
        #pragma unroll
        for (int i = 0; i < 2; i++) {
            int cc = i * 128 + tid;
            int r = cc >> 2, off = cc & 3;
            CPA16(smem_u32(ms + r * 80 + off * 16),
                  mbase + (size_t)(q0 + r) * Sn + kt0 + off * 16);
        }
    };

    issue(0);
    CPA_COMMIT();

    for (int kt16 = 0; kt16 < 16; kt16++) {
        if (kt16 + 1 < 16) { issue(kt16 + 1); CPA_COMMIT(); CPA_WAIT1(); }
        else               { CPA_WAIT0(); }
        __syncthreads();    // tile kt16 visible to all warps

        char* st = dsm + (kt16 & 1) * KVSTAGE;
        char* sKh = st;
        char* sKl = st + 64 * AST;
        char* sVh = st + 2 * 64 * AST;
        char* sVl = st + 3 * 64 * AST;
        unsigned char* Ms = (unsigned char*)(dsm + MOFF + (kt16 & 1) * MSTAGE);
        const int kt0 = kt16 * 64;

        // S = Q K^T (3x split), scores in log2 units
        float S[8][4];
        #pragma unroll
        for (int nt = 0; nt < 8; nt++)
            #pragma unroll
            for (int e = 0; e < 4; e++) S[nt][e] = 0.f;
        #pragma unroll
        for (int kt = 0; kt < 4; kt++) {
            #pragma unroll
            for (int ntp = 0; ntp < 4; ntp++) {
                int r = (ntp * 2 + (sub >> 1)) * 8 + (lane & 7);
                int kb = kt * 32 + (sub & 1) * 16;
                unsigned th[4], tl[4];
                ldsm4(th, smem_u32(sKh + r * AST + kb));
                ldsm4(tl, smem_u32(sKl + r * AST + kb));
                mma16816(S[2 * ntp],     qh[kt], th);
                mma16816(S[2 * ntp],     qh[kt], tl);
                mma16816(S[2 * ntp],     ql[kt], th);
                mma16816(S[2 * ntp + 1], qh[kt], th + 2);
                mma16816(S[2 * ntp + 1], qh[kt], tl + 2);
                mma16816(S[2 * ntp + 1], ql[kt], th + 2);
            }
        }

        // graph prefetch (last head only)
        float2 gA[8], gB[8];
        if (lastH) {
            #pragma unroll
            for (int nt = 0; nt < 8; nt++) {
                int col = kt0 + nt * 8 + 2 * t;
                gA[nt] = *(const float2*)(gbase + (size_t)(q0 + rA) * Sn + col);
                gB[nt] = *(const float2*)(gbase + (size_t)(q0 + rB) * Sn + col);
            }
        }

        // p = 2^s (FMA-only), mask -> 0, graph fused; accumulate l
        float la = 0.f, lb = 0.f;
        #pragma unroll
        for (int nt = 0; nt < 8; nt++) {
            const int col = nt * 8 + 2 * t;
            float p0 = exp2p(S[nt][0]);
            float p1 = exp2p(S[nt][1]);
            float p2 = exp2p(S[nt][2]);
            float p3 = exp2p(S[nt][3]);
            if (Ms[rA * 80 + col])     p0 = 0.f;
            if (Ms[rA * 80 + col + 1]) p1 = 0.f;
            if (Ms[rB * 80 + col])     p2 = 0.f;
            if (Ms[rB * 80 + col + 1]) p3 = 0.f;
            if (lastH) {
                p0 *= gA[nt].x; p1 *= gA[nt].y;
                p2 *= gB[nt].x; p3 *= gB[nt].y;
            }
            S[nt][0] = p0; S[nt][1] = p1; S[nt][2] = p2; S[nt][3] = p3;
            la += p0 + p1; lb += p2 + p3;
        }
        lA += la; lB += lb;

        // O += P V (3x split); V via ldmatrix.trans
        #pragma unroll
        for (int kt = 0; kt < 4; kt++) {
            unsigned ph[4], pl[4];
            split_pack(S[2 * kt][0],     S[2 * kt][1],     ph[0], pl[0]);
            split_pack(S[2 * kt][2],     S[2 * kt][3],     ph[1], pl[1]);
            split_pack(S[2 * kt + 1][0], S[2 * kt + 1][1], ph[2], pl[2]);
            split_pack(S[2 * kt + 1][2], S[2 * kt + 1][3], ph[3], pl[3]);
            #pragma unroll
            for (int ntp = 0; ntp < 4; ntp++) {
                int r = kt * 16 + (sub & 1) * 8 + (lane & 7);
                int cb = (2 * ntp + (sub >> 1)) * 16;
                unsigned th[4], tl[4];
                ldsm4t(th, smem_u32(sVh + r * AST + cb));
                ldsm4t(tl, smem_u32(sVl + r * AST + cb));
                mma16816(O[2 * ntp],     ph, th);
                mma16816(O[2 * ntp],     ph, tl);
                mma16816(O[2 * ntp],     pl, th);
                mma16816(O[2 * ntp + 1], ph, th + 2);
                mma16816(O[2 * ntp + 1], ph, tl + 2);
                mma16816(O[2 * ntp + 1], pl, th + 2);
            }
        }
        __syncthreads();    // all warps done with this buffer before it is re-filled
    }

    lA += __shfl_xor_sync(0xffffffff, lA, 1);
    lA += __shfl_xor_sync(0xffffffff, lA, 2);
    lB += __shfl_xor_sync(0xffffffff, lB, 1);
    lB += __shfl_xor_sync(0xffffffff, lB, 2);
    const float invA = 1.f / lA, invB = 1.f / lB;

    const int rowA = q0 + rA, rowB = q0 + rB;
    #pragma unroll
    for (int nt = 0; nt < 8; nt++) {
        const int col = hh * DHn + nt * 8 + 2 * t;
        unsigned hw, lw;
        split_pack(O[nt][0] * invA, O[nt][1] * invA, hw, lw);
        *(unsigned*)(ctxh + (size_t)(b * Sn + rowA) * Dn + col) = hw;
        *(unsigned*)(ctxl + (size_t)(b * Sn + rowA) * Dn + col) = lw;
        split_pack(O[nt][2] * invB, O[nt][3] * invB, hw, lw);
        *(unsigned*)(ctxh + (size_t)(b * Sn + rowB) * Dn + col) = hw;
        *(unsigned*)(ctxl + (size_t)(b * Sn + rowB) * Dn + col) = lw;
    }
}

// ---------------------------------------------------------------------------
// Launch
// ---------------------------------------------------------------------------
extern "C" void kernel_launch(void* const* d_in, const int* in_sizes, int n_in,
                              void* d_out, int out_size)
{
    const float* key   = (const float*)d_in[0];
    const float* value = (const float*)d_in[1];
    const float* query = (const float*)d_in[2];
    const int*   mask  = (const int*)d_in[3];
    const float* graph = (const float*)d_in[4];
    const float* Wq = (const float*)d_in[5];
    const float* bq = (const float*)d_in[6];
    const float* Wk = (const float*)d_in[7];
    const float* bk = (const float*)d_in[8];
    const float* Wv = (const float*)d_in[9];
    const float* bv = (const float*)d_in[10];
    const float* Wo = (const float*)d_in[11];
    const float* bo = (const float*)d_in[12];
    float* out = (float*)d_out;

    static int inited = 0;
    if (!inited) {
        cudaFuncSetAttribute(gemm_bf16x3, cudaFuncAttributeMaxDynamicSharedMemorySize, 81920);
        cudaFuncSetAttribute(attn_mma, cudaFuncAttributeMaxDynamicSharedMemorySize, ATTN_SMEM);
        inited = 1;
    }

    #define SYM(p, s) void* p; cudaGetSymbolAddress(&p, s)
    SYM(iqh, gin_qh); SYM(iql, gin_ql);
    SYM(ikh, gin_kh); SYM(ikl, gin_kl);
    SYM(ivh, gin_vh); SYM(ivl, gin_vl);
    SYM(wqh, gWqh); SYM(wql, gWql);
    SYM(wkh, gWkh); SYM(wkl, gWkl);
    SYM(wvh, gWvh); SYM(wvl, gWvl);
    SYM(woh, gWoh); SYM(wol, gWol);
    SYM(pqh, g_qh); SYM(pql, g_ql);
    SYM(pkh, g_kh); SYM(pkl, g_kl);
    SYM(pvh, g_vh); SYM(pvl, g_vl);
    SYM(cxh, g_ctxh); SYM(cxl, g_ctxl);
    SYM(mpk, g_mask);
    #undef SYM

    typedef __nv_bfloat16 bf;
    const int nIn = Mn * Dn / 2, nW = Dn * Dn / 2;
    split_in3<<<dim3((nIn + 255) / 256, 3), 256>>>(
        query, key, value,
        (bf*)iqh, (bf*)iql, (bf*)ikh, (bf*)ikl, (bf*)ivh, (bf*)ivl, nIn);
    split_in4<<<dim3((nW + 255) / 256, 4), 256>>>(
        Wq, Wk, Wv, Wo,
        (bf*)wqh, (bf*)wql, (bf*)wkh, (bf*)wkl,
        (bf*)wvh, (bf*)wvl, (bf*)woh, (bf*)wol, nW);
    const int nM4 = Bn * Sn * Sn / 4;
    pack_mask<<<(nM4 + 255) / 256, 256>>>((const int4*)mask, (uchar4*)mpk, nM4);

    const float QSCALE = 0.125f * 1.4426950408889634f;   // fold log2e into Q
    dim3 ggrid(Dn / 128, Mn / 128);
    gemm_bf16x3<<<ggrid, 256, 81920>>>((bf*)iqh, (bf*)iql, (bf*)wqh, (bf*)wql, bq,
                                       nullptr, (bf*)pqh, (bf*)pql, 0, QSCALE);
    gemm_bf16x3<<<ggrid, 256, 81920>>>((bf*)ikh, (bf*)ikl, (bf*)wkh, (bf*)wkl, bk,
                                       nullptr, (bf*)pkh, (bf*)pkl, 0, 1.0f);
    gemm_bf16x3<<<ggrid, 256, 81920>>>((bf*)ivh, (bf*)ivl, (bf*)wvh, (bf*)wvl, bv,
                                       nullptr, (bf*)pvh, (bf*)pvl, 0, 1.0f);

    attn_mma<<<dim3(Sn / 64, Hn, Bn), 128, ATTN_SMEM>>>(
        (const bf*)pqh, (const bf*)pql, (const bf*)pkh, (const bf*)pkl,
        (const bf*)pvh, (const bf*)pvl, (const unsigned char*)mpk, graph,
        (bf*)cxh, (bf*)cxl);

    gemm_bf16x3<<<ggrid, 256, 81920>>>((const bf*)cxh, (const bf*)cxl,
                                       (bf*)woh, (bf*)wol, bo,
                                       out, nullptr, nullptr, 2, 1.0f);
}

// round 8
// speedup vs baseline: 3.7158x; 1.0581x over previous
#include <cuda_runtime.h>
#include <cuda_bf16.h>
#include <math_constants.h>

#define Bn  8
#define Sn  1024
#define Dn  1024
#define Hn  16
#define DHn 64
#define Mn  (Bn * Sn)   // 8192

// ---------------------------------------------------------------------------
// Device-global scratch
// ---------------------------------------------------------------------------
__device__ __nv_bfloat16 gin_qh[Mn * Dn], gin_ql[Mn * Dn];
__device__ __nv_bfloat16 gin_kh[Mn * Dn], gin_kl[Mn * Dn];
__device__ __nv_bfloat16 gin_vh[Mn * Dn], gin_vl[Mn * Dn];
__device__ __nv_bfloat16 gWqh[Dn * Dn], gWql[Dn * Dn];
__device__ __nv_bfloat16 gWkh[Dn * Dn], gWkl[Dn * Dn];
__device__ __nv_bfloat16 gWvh[Dn * Dn], gWvl[Dn * Dn];
__device__ __nv_bfloat16 gWoh[Dn * Dn], gWol[Dn * Dn];
__device__ __nv_bfloat16 g_qh[Mn * Dn], g_ql[Mn * Dn];   // [B,H,S,DH]
__device__ __nv_bfloat16 g_kh[Mn * Dn], g_kl[Mn * Dn];
__device__ __nv_bfloat16 g_vh[Mn * Dn], g_vl[Mn * Dn];
__device__ __nv_bfloat16 g_ctxh[Mn * Dn], g_ctxl[Mn * Dn]; // [B,S,D]
__device__ unsigned char g_mask[Bn * Sn * Sn];             // packed mask bytes

// ---------------------------------------------------------------------------
// helpers
// ---------------------------------------------------------------------------
__device__ __forceinline__ unsigned smem_u32(const void* p) {
    return (unsigned)__cvta_generic_to_shared(p);
}
__device__ __forceinline__ void mma16816(float* c, const unsigned* a, const unsigned* b) {
    asm volatile(
        "mma.sync.aligned.m16n8k16.row.col.f32.bf16.bf16.f32 "
        "{%0,%1,%2,%3},{%4,%5,%6,%7},{%8,%9},{%0,%1,%2,%3};\n"
        : "+f"(c[0]), "+f"(c[1]), "+f"(c[2]), "+f"(c[3])
        : "r"(a[0]), "r"(a[1]), "r"(a[2]), "r"(a[3]), "r"(b[0]), "r"(b[1]));
}
__device__ __forceinline__ void ldsm4(unsigned* r, unsigned addr) {
    asm volatile("ldmatrix.sync.aligned.m8n8.x4.shared.b16 {%0,%1,%2,%3},[%4];\n"
                 : "=r"(r[0]), "=r"(r[1]), "=r"(r[2]), "=r"(r[3]) : "r"(addr));
}
__device__ __forceinline__ void ldsm4t(unsigned* r, unsigned addr) {
    asm volatile("ldmatrix.sync.aligned.m8n8.x4.trans.shared.b16 {%0,%1,%2,%3},[%4];\n"
                 : "=r"(r[0]), "=r"(r[1]), "=r"(r[2]), "=r"(r[3]) : "r"(addr));
}
__device__ __forceinline__ void split_pack(float x, float y, unsigned& hi, unsigned& lo) {
    __nv_bfloat16 hx = __float2bfloat16(x);
    __nv_bfloat16 hy = __float2bfloat16(y);
    float rx = x - __bfloat162float(hx);
    float ry = y - __bfloat162float(hy);
    __nv_bfloat162 h; h.x = hx; h.y = hy;
    __nv_bfloat162 l; l.x = __float2bfloat16(rx); l.y = __float2bfloat16(ry);
    hi = *(unsigned*)&h;
    lo = *(unsigned*)&l;
}
// fast 2^y, FMA-only (no MUFU)
__device__ __forceinline__ float exp2p(float y) {
    y = fmaxf(fminf(y, 60.f), -60.f);
    float z = y + 12582912.f;              // 1.5*2^23
    int i = __float_as_int(z) << 23;
    float f = y - (z - 12582912.f);
    float p = 1.3333558e-3f;
    p = fmaf(p, f, 9.6181291e-3f);
    p = fmaf(p, f, 5.5504109e-2f);
    p = fmaf(p, f, 2.4022651e-1f);
    p = fmaf(p, f, 6.9314718e-1f);
    p = fmaf(p, f, 1.0f);
    return __int_as_float(__float_as_int(p) + i);
}
#define CPA16(smem, gmem) asm volatile("cp.async.cg.shared.global [%0], [%1], 16;\n" :: "r"(smem), "l"(gmem))
#define CPA_COMMIT()      asm volatile("cp.async.commit_group;\n")
#define CPA_WAIT0()       asm volatile("cp.async.wait_group 0;\n" ::: "memory")
#define CPA_WAIT1()       asm volatile("cp.async.wait_group 1;\n" ::: "memory")

// ---------------------------------------------------------------------------
// Pre-split kernels + mask pack
// ---------------------------------------------------------------------------
__device__ __forceinline__ void do_split(const float* src, __nv_bfloat16* hi,
                                         __nv_bfloat16* lo, int i) {
    float2 v = ((const float2*)src)[i];
    unsigned h, l;
    split_pack(v.x, v.y, h, l);
    ((unsigned*)hi)[i] = h;
    ((unsigned*)lo)[i] = l;
}
__global__ void split_in3(const float* __restrict__ s0, const float* __restrict__ s1,
                          const float* __restrict__ s2,
                          __nv_bfloat16* h0, __nv_bfloat16* l0,
                          __nv_bfloat16* h1, __nv_bfloat16* l1,
                          __nv_bfloat16* h2, __nv_bfloat16* l2, int n2)
{
    int i = blockIdx.x * blockDim.x + threadIdx.x;
    if (i >= n2) return;
    switch (blockIdx.y) {
        case 0: do_split(s0, h0, l0, i); break;
        case 1: do_split(s1, h1, l1, i); break;
        default: do_split(s2, h2, l2, i); break;
    }
}
__global__ void split_in4(const float* __restrict__ s0, const float* __restrict__ s1,
                          const float* __restrict__ s2, const float* __restrict__ s3,
                          __nv_bfloat16* h0, __nv_bfloat16* l0,
                          __nv_bfloat16* h1, __nv_bfloat16* l1,
                          __nv_bfloat16* h2, __nv_bfloat16* l2,
                          __nv_bfloat16* h3, __nv_bfloat16* l3, int n2)
{
    int i = blockIdx.x * blockDim.x + threadIdx.x;
    if (i >= n2) return;
    switch (blockIdx.y) {
        case 0: do_split(s0, h0, l0, i); break;
        case 1: do_split(s1, h1, l1, i); break;
        case 2: do_split(s2, h2, l2, i); break;
        default: do_split(s3, h3, l3, i); break;
    }
}
__global__ void pack_mask(const int4* __restrict__ m, uchar4* __restrict__ o, int n4)
{
    int i = blockIdx.x * blockDim.x + threadIdx.x;
    if (i < n4) {
        int4 v = m[i];
        o[i] = make_uchar4((unsigned char)(v.x != 0), (unsigned char)(v.y != 0),
                           (unsigned char)(v.z != 0), (unsigned char)(v.w != 0));
    }
}

// ---------------------------------------------------------------------------
// Split-bf16 (3x) GEMM body, cp.async double-buffered, term-outer mma order.
// C = A[M,K] @ W[N,K]^T + bias. Block 128x128, BK=32, 256 thr (2x4 warps).
// mode 0: head-split bf16 hi/lo out, scaled. mode 2: plain fp32 out.
// ---------------------------------------------------------------------------
#define GST 80  // bytes per smem row (64B data + 16B pad)

__device__ __forceinline__
void gemm_body(char* dsm,
               const __nv_bfloat16* __restrict__ Ahi, const __nv_bfloat16* __restrict__ Alo,
               const __nv_bfloat16* __restrict__ Whi, const __nv_bfloat16* __restrict__ Wlo,
               const float* __restrict__ bias,
               float* __restrict__ Cf,
               __nv_bfloat16* __restrict__ Ch, __nv_bfloat16* __restrict__ Cl,
               int mode, float scale, int m0, int n0)
{
    const int tid = threadIdx.x;
    const int wid = tid >> 5, lane = tid & 31;
    const int wm = wid >> 2, wn = wid & 3;
    const int g = lane >> 2, t = lane & 3;
    const int sub = lane >> 3;

    float c[4][4][4];
    #pragma unroll
    for (int mt = 0; mt < 4; mt++)
        #pragma unroll
        for (int nt = 0; nt < 4; nt++)
            #pragma unroll
            for (int e = 0; e < 4; e++) c[mt][nt][e] = 0.f;

    auto issue = [&](int k0, int buf) {
        char* st = dsm + buf * 40960;
        #pragma unroll
        for (int i = 0; i < 2; i++) {
            int cc = i * 256 + tid;
            int r = cc >> 2, off = cc & 3;
            size_t ga = (size_t)(m0 + r) * Dn + k0 + off * 8;
            size_t gw = (size_t)(n0 + r) * Dn + k0 + off * 8;
            unsigned sa = smem_u32(st + r * GST + off * 16);
            CPA16(sa,         Ahi + ga);
            CPA16(sa + 10240, Alo + ga);
            CPA16(sa + 20480, Whi + gw);
            CPA16(sa + 30720, Wlo + gw);
        }
    };

    issue(0, 0);
    CPA_COMMIT();

    for (int it = 0; it < Dn / 32; it++) {
        CPA_WAIT0();
        __syncthreads();
        if (it + 1 < Dn / 32) { issue((it + 1) * 32, (it + 1) & 1); CPA_COMMIT(); }

        char* st = dsm + (it & 1) * 40960;
        char* sAh = st; char* sAl = st + 10240;
        char* sWh = st + 20480; char* sWl = st + 30720;

        #pragma unroll
        for (int kt = 0; kt < 2; kt++) {
            unsigned ah[4][4], al[4][4], bh[4][2], bl[4][2];
            #pragma unroll
            for (int mt = 0; mt < 4; mt++) {
                int r = wm * 64 + mt * 16 + (lane & 7) + (sub & 1) * 8;
                int kb = kt * 32 + (sub >> 1) * 16;
                ldsm4(ah[mt], smem_u32(sAh + r * GST + kb));
                ldsm4(al[mt], smem_u32(sAl + r * GST + kb));
            }
            #pragma unroll
            for (int ntp = 0; ntp < 2; ntp++) {
                int r = wn * 32 + (ntp * 2 + (sub >> 1)) * 8 + (lane & 7);
                int kb = kt * 32 + (sub & 1) * 16;
                unsigned tmp[4];
                ldsm4(tmp, smem_u32(sWh + r * GST + kb));
                bh[2 * ntp][0] = tmp[0]; bh[2 * ntp][1] = tmp[1];
                bh[2 * ntp + 1][0] = tmp[2]; bh[2 * ntp + 1][1] = tmp[3];
                ldsm4(tmp, smem_u32(sWl + r * GST + kb));
                bl[2 * ntp][0] = tmp[0]; bl[2 * ntp][1] = tmp[1];
                bl[2 * ntp + 1][0] = tmp[2]; bl[2 * ntp + 1][1] = tmp[3];
            }
            // term-outer: 16 independent accumulators between same-acc reuse
            #pragma unroll
            for (int mt = 0; mt < 4; mt++)
                #pragma unroll
                for (int nt = 0; nt < 4; nt++)
                    mma16816(c[mt][nt], ah[mt], bh[nt]);
            #pragma unroll
            for (int mt = 0; mt < 4; mt++)
                #pragma unroll
                for (int nt = 0; nt < 4; nt++)
                    mma16816(c[mt][nt], ah[mt], bl[nt]);
            #pragma unroll
            for (int mt = 0; mt < 4; mt++)
                #pragma unroll
                for (int nt = 0; nt < 4; nt++)
                    mma16816(c[mt][nt], al[mt], bh[nt]);
        }
    }

    #pragma unroll
    for (int mt = 0; mt < 4; mt++) {
        #pragma unroll
        for (int nt = 0; nt < 4; nt++) {
            const int row = m0 + wm * 64 + mt * 16 + g;
            const int col = n0 + wn * 32 + nt * 8 + 2 * t;
            const float b0 = bias[col], b1 = bias[col + 1];
            #pragma unroll
            for (int half = 0; half < 2; half++) {
                const int r = row + half * 8;
                const float v0 = (c[mt][nt][half * 2 + 0] + b0) * scale;
                const float v1 = (c[mt][nt][half * 2 + 1] + b1) * scale;
                if (mode == 2) {
                    *(float2*)(Cf + (size_t)r * Dn + col) = make_float2(v0, v1);
                } else {
                    const int bb = r >> 10, s = r & 1023;
                    const int hh = col >> 6, d = col & 63;
                    size_t idx = (((size_t)(bb * Hn + hh) * Sn + s) * DHn) + d;
                    unsigned hw, lw;
                    split_pack(v0, v1, hw, lw);
                    *(unsigned*)(Ch + idx) = hw;
                    *(unsigned*)(Cl + idx) = lw;
                }
            }
        }
    }
}

// fused Q/K/V projections: blockIdx.z selects the matmul
__global__ __launch_bounds__(256)
void gemm_qkv(const __nv_bfloat16* Ah0, const __nv_bfloat16* Al0,
              const __nv_bfloat16* Ah1, const __nv_bfloat16* Al1,
              const __nv_bfloat16* Ah2, const __nv_bfloat16* Al2,
              const __nv_bfloat16* Wh0, const __nv_bfloat16* Wl0,
              const __nv_bfloat16* Wh1, const __nv_bfloat16* Wl1,
              const __nv_bfloat16* Wh2, const __nv_bfloat16* Wl2,
              const float* b0, const float* b1, const float* b2,
              __nv_bfloat16* Ch0, __nv_bfloat16* Cl0,
              __nv_bfloat16* Ch1, __nv_bfloat16* Cl1,
              __nv_bfloat16* Ch2, __nv_bfloat16* Cl2,
              float sc0)
{
    extern __shared__ __align__(16) char dsm[];
    const int m0 = blockIdx.y * 128, n0 = blockIdx.x * 128;
    switch (blockIdx.z) {
        case 0: gemm_body(dsm, Ah0, Al0, Wh0, Wl0, b0, nullptr, Ch0, Cl0, 0, sc0, m0, n0); break;
        case 1: gemm_body(dsm, Ah1, Al1, Wh1, Wl1, b1, nullptr, Ch1, Cl1, 0, 1.0f, m0, n0); break;
        default: gemm_body(dsm, Ah2, Al2, Wh2, Wl2, b2, nullptr, Ch2, Cl2, 0, 1.0f, m0, n0); break;
    }
}

__global__ __launch_bounds__(256)
void gemm_o(const __nv_bfloat16* Ah, const __nv_bfloat16* Al,
            const __nv_bfloat16* Wh, const __nv_bfloat16* Wl,
            const float* bias, float* Cf)
{
    extern __shared__ __align__(16) char dsm[];
    gemm_body(dsm, Ah, Al, Wh, Wl, bias, Cf, nullptr, nullptr, 2, 1.0f,
              blockIdx.y * 128, blockIdx.x * 128);
}

// ---------------------------------------------------------------------------
// Tensor-core flash attention, MUFU-free softmax, double-buffered K/V/mask,
// term-outer mma ordering (8 independent accumulators between reuse).
// ---------------------------------------------------------------------------
#define AST 144                 // bytes per K/V smem row (128B data + 16B pad)
#define KVSTAGE (4 * 64 * AST)  // 36864 per stage (Kh,Kl,Vh,Vl)
#define MOFF (2 * KVSTAGE)
#define MSTAGE (64 * 80)
#define ATTN_SMEM (MOFF + 2 * MSTAGE)  // 83968

__global__ __launch_bounds__(128, 2)
void attn_mma(const __nv_bfloat16* __restrict__ qh_g, const __nv_bfloat16* __restrict__ ql_g,
              const __nv_bfloat16* __restrict__ kh_g, const __nv_bfloat16* __restrict__ kl_g,
              const __nv_bfloat16* __restrict__ vh_g, const __nv_bfloat16* __restrict__ vl_g,
              const unsigned char* __restrict__ maskp, const float* __restrict__ graph,
              __nv_bfloat16* __restrict__ ctxh, __nv_bfloat16* __restrict__ ctxl)
{
    extern __shared__ __align__(16) char dsm[];

    const int tid = threadIdx.x;
    const int w = tid >> 5, lane = tid & 31;
    const int g = lane >> 2, t = lane & 3;
    const int sub = lane >> 3;
    const int hh = blockIdx.y, b = blockIdx.z;
    const int q0 = blockIdx.x * 64;
    const bool lastH = (hh == Hn - 1);

    const size_t hoff = (size_t)((b * Hn + hh) * Sn) * DHn;
    const unsigned char* mbase = maskp + (size_t)(b * Sn) * Sn;
    const float* gbase = graph + (size_t)(b * Sn) * Sn;

    unsigned qh[4][4], ql[4][4];
    {
        const __nv_bfloat16* qb_h = qh_g + hoff + (size_t)(q0 + w * 16) * DHn;
        const __nv_bfloat16* qb_l = ql_g + hoff + (size_t)(q0 + w * 16) * DHn;
        #pragma unroll
        for (int kt = 0; kt < 4; kt++) {
            int c0 = kt * 16 + 2 * t;
            qh[kt][0] = *(const unsigned*)(qb_h + (size_t)g * DHn + c0);
            qh[kt][1] = *(const unsigned*)(qb_h + (size_t)(g + 8) * DHn + c0);
            qh[kt][2] = *(const unsigned*)(qb_h + (size_t)g * DHn + c0 + 8);
            qh[kt][3] = *(const unsigned*)(qb_h + (size_t)(g + 8) * DHn + c0 + 8);
            ql[kt][0] = *(const unsigned*)(qb_l + (size_t)g * DHn + c0);
            ql[kt][1] = *(const unsigned*)(qb_l + (size_t)(g + 8) * DHn + c0);
            ql[kt][2] = *(const unsigned*)(qb_l + (size_t)g * DHn + c0 + 8);
            ql[kt][3] = *(const unsigned*)(qb_l + (size_t)(g + 8) * DHn + c0 + 8);
        }
    }

    float O[8][4];
    #pragma unroll
    for (int nt = 0; nt < 8; nt++)
        #pragma unroll
        for (int e = 0; e < 4; e++) O[nt][e] = 0.f;
    float lA = 0.f, lB = 0.f;
    const int rA = w * 16 + g, rB = rA + 8;

    auto issue = [&](int kt16) {
        const int buf = kt16 & 1;
        char* st = dsm + buf * KVSTAGE;
        const int kt0 = kt16 * 64;
        #pragma unroll
        for (int i = 0; i < 4; i++) {
            int cc = i * 128 + tid;
            int r = cc >> 3, off = cc & 7;
            size_t gsrc = hoff + (size_t)(kt0 + r) * DHn + off * 8;
            CPA16(smem_u32(st + r * AST + off * 16),                kh_g + gsrc);
            CPA16(smem_u32(st + 64 * AST + r * AST + off * 16),     kl_g + gsrc);
            CPA16(smem_u32(st + 2 * 64 * AST + r * AST + off * 16), vh_g + gsrc);
            CPA16(smem_u32(st + 3 * 64 * AST + r * AST + off * 16), vl_g + gsrc);
        }
        char* ms = dsm + MOFF + buf * MSTAGE;
        #pragma unroll
        for (int i = 0; i < 2; i++) {
            int cc = i * 128 + tid;
            int r = cc >> 2, off = cc & 3;
            CPA16(smem_u32(ms + r * 80 + off * 16),
                  mbase + (size_t)(q0 + r) * Sn + kt0 + off * 16);
        }
    };

    issue(0);
    CPA_COMMIT();

    for (int kt16 = 0; kt16 < 16; kt16++) {
        if (kt16 + 1 < 16) { issue(kt16 + 1); CPA_COMMIT(); CPA_WAIT1(); }
        else               { CPA_WAIT0(); }
        __syncthreads();

        char* st = dsm + (kt16 & 1) * KVSTAGE;
        char* sKh = st;
        char* sKl = st + 64 * AST;
        char* sVh = st + 2 * 64 * AST;
        char* sVl = st + 3 * 64 * AST;
        unsigned char* Ms = (unsigned char*)(dsm + MOFF + (kt16 & 1) * MSTAGE);
        const int kt0 = kt16 * 64;

        // S = Q K^T (3x split), term-outer issue order
        float S[8][4];
        #pragma unroll
        for (int nt = 0; nt < 8; nt++)
            #pragma unroll
            for (int e = 0; e < 4; e++) S[nt][e] = 0.f;
        #pragma unroll
        for (int kt = 0; kt < 4; kt++) {
            unsigned th[4][4], tl[4][4];
            #pragma unroll
            for (int ntp = 0; ntp < 4; ntp++) {
                int r = (ntp * 2 + (sub >> 1)) * 8 + (lane & 7);
                int kb = kt * 32 + (sub & 1) * 16;
                ldsm4(th[ntp], smem_u32(sKh + r * AST + kb));
                ldsm4(tl[ntp], smem_u32(sKl + r * AST + kb));
            }
            #pragma unroll
            for (int ntp = 0; ntp < 4; ntp++) {
                mma16816(S[2 * ntp],     qh[kt], th[ntp]);
                mma16816(S[2 * ntp + 1], qh[kt], th[ntp] + 2);
            }
            #pragma unroll
            for (int ntp = 0; ntp < 4; ntp++) {
                mma16816(S[2 * ntp],     qh[kt], tl[ntp]);
                mma16816(S[2 * ntp + 1], qh[kt], tl[ntp] + 2);
            }
            #pragma unroll
            for (int ntp = 0; ntp < 4; ntp++) {
                mma16816(S[2 * ntp],     ql[kt], th[ntp]);
                mma16816(S[2 * ntp + 1], ql[kt], th[ntp] + 2);
            }
        }

        float2 gA[8], gB[8];
        if (lastH) {
            #pragma unroll
            for (int nt = 0; nt < 8; nt++) {
                int col = kt0 + nt * 8 + 2 * t;
                gA[nt] = *(const float2*)(gbase + (size_t)(q0 + rA) * Sn + col);
                gB[nt] = *(const float2*)(gbase + (size_t)(q0 + rB) * Sn + col);
            }
        }

        float la = 0.f, lb = 0.f;
        #pragma unroll
        for (int nt = 0; nt < 8; nt++) {
            const int col = nt * 8 + 2 * t;
            float p0 = exp2p(S[nt][0]);
            float p1 = exp2p(S[nt][1]);
            float p2 = exp2p(S[nt][2]);
            float p3 = exp2p(S[nt][3]);
            if (Ms[rA * 80 + col])     p0 = 0.f;
            if (Ms[rA * 80 + col + 1]) p1 = 0.f;
            if (Ms[rB * 80 + col])     p2 = 0.f;
            if (Ms[rB * 80 + col + 1]) p3 = 0.f;
            if (lastH) {
                p0 *= gA[nt].x; p1 *= gA[nt].y;
                p2 *= gB[nt].x; p3 *= gB[nt].y;
            }
            S[nt][0] = p0; S[nt][1] = p1; S[nt][2] = p2; S[nt][3] = p3;
            la += p0 + p1; lb += p2 + p3;
        }
        lA += la; lB += lb;

        // O += P V (3x split), term-outer issue order
        #pragma unroll
        for (int kt = 0; kt < 4; kt++) {
            unsigned ph[4], pl[4];
            split_pack(S[2 * kt][0],     S[2 * kt][1],     ph[0], pl[0]);
            split_pack(S[2 * kt][2],     S[2 * kt][3],     ph[1], pl[1]);
            split_pack(S[2 * kt + 1][0], S[2 * kt + 1][1], ph[2], pl[2]);
            split_pack(S[2 * kt + 1][2], S[2 * kt + 1][3], ph[3], pl[3]);
            unsigned th[4][4], tl[4][4];
            #pragma unroll
            for (int ntp = 0; ntp < 4; ntp++) {
                int r = kt * 16 + (sub & 1) * 8 + (lane & 7);
                int cb = (2 * ntp + (sub >> 1)) * 16;
                ldsm4t(th[ntp], smem_u32(sVh + r * AST + cb));
                ldsm4t(tl[ntp], smem_u32(sVl + r * AST + cb));
            }
            #pragma unroll
            for (int ntp = 0; ntp < 4; ntp++) {
                mma16816(O[2 * ntp],     ph, th[ntp]);
                mma16816(O[2 * ntp + 1], ph, th[ntp] + 2);
            }
            #pragma unroll
            for (int ntp = 0; ntp < 4; ntp++) {
                mma16816(O[2 * ntp],     ph, tl[ntp]);
                mma16816(O[2 * ntp + 1], ph, tl[ntp] + 2);
            }
            #pragma unroll
            for (int ntp = 0; ntp < 4; ntp++) {
                mma16816(O[2 * ntp],     pl, th[ntp]);
                mma16816(O[2 * ntp + 1], pl, th[ntp] + 2);
            }
        }
        __syncthreads();
    }

    lA += __shfl_xor_sync(0xffffffff, lA, 1);
    lA += __shfl_xor_sync(0xffffffff, lA, 2);
    lB += __shfl_xor_sync(0xffffffff, lB, 1);
    lB += __shfl_xor_sync(0xffffffff, lB, 2);
    const float invA = 1.f / lA, invB = 1.f / lB;

    const int rowA = q0 + rA, rowB = q0 + rB;
    #pragma unroll
    for (int nt = 0; nt < 8; nt++) {
        const int col = hh * DHn + nt * 8 + 2 * t;
        unsigned hw, lw;
        split_pack(O[nt][0] * invA, O[nt][1] * invA, hw, lw);
        *(unsigned*)(ctxh + (size_t)(b * Sn + rowA) * Dn + col) = hw;
        *(unsigned*)(ctxl + (size_t)(b * Sn + rowA) * Dn + col) = lw;
        split_pack(O[nt][2] * invB, O[nt][3] * invB, hw, lw);
        *(unsigned*)(ctxh + (size_t)(b * Sn + rowB) * Dn + col) = hw;
        *(unsigned*)(ctxl + (size_t)(b * Sn + rowB) * Dn + col) = lw;
    }
}

// ---------------------------------------------------------------------------
// Launch
// ---------------------------------------------------------------------------
extern "C" void kernel_launch(void* const* d_in, const int* in_sizes, int n_in,
                              void* d_out, int out_size)
{
    const float* key   = (const float*)d_in[0];
    const float* value = (const float*)d_in[1];
    const float* query = (const float*)d_in[2];
    const int*   mask  = (const int*)d_in[3];
    const float* graph = (const float*)d_in[4];
    const float* Wq = (const float*)d_in[5];
    const float* bq = (const float*)d_in[6];
    const float* Wk = (const float*)d_in[7];
    const float* bk = (const float*)d_in[8];
    const float* Wv = (const float*)d_in[9];
    const float* bv = (const float*)d_in[10];
    const float* Wo = (const float*)d_in[11];
    const float* bo = (const float*)d_in[12];
    float* out = (float*)d_out;

    static int inited = 0;
    if (!inited) {
        cudaFuncSetAttribute(gemm_qkv, cudaFuncAttributeMaxDynamicSharedMemorySize, 81920);
        cudaFuncSetAttribute(gemm_o, cudaFuncAttributeMaxDynamicSharedMemorySize, 81920);
        cudaFuncSetAttribute(attn_mma, cudaFuncAttributeMaxDynamicSharedMemorySize, ATTN_SMEM);
        inited = 1;
    }

    #define SYM(p, s) void* p; cudaGetSymbolAddress(&p, s)
    SYM(iqh, gin_qh); SYM(iql, gin_ql);
    SYM(ikh, gin_kh); SYM(ikl, gin_kl);
    SYM(ivh, gin_vh); SYM(ivl, gin_vl);
    SYM(wqh, gWqh); SYM(wql, gWql);
    SYM(wkh, gWkh); SYM(wkl, gWkl);
    SYM(wvh, gWvh); SYM(wvl, gWvl);
    SYM(woh, gWoh); SYM(wol, gWol);
    SYM(pqh, g_qh); SYM(pql, g_ql);
    SYM(pkh, g_kh); SYM(pkl, g_kl);
    SYM(pvh, g_vh); SYM(pvl, g_vl);
    SYM(cxh, g_ctxh); SYM(cxl, g_ctxl);
    SYM(mpk, g_mask);
    #undef SYM

    typedef __nv_bfloat16 bf;
    const int nIn = Mn * Dn / 2, nW = Dn * Dn / 2;
    split_in3<<<dim3((nIn + 255) / 256, 3), 256>>>(
        query, key, value,
        (bf*)iqh, (bf*)iql, (bf*)ikh, (bf*)ikl, (bf*)ivh, (bf*)ivl, nIn);
    split_in4<<<dim3((nW + 255) / 256, 4), 256>>>(
        Wq, Wk, Wv, Wo,
        (bf*)wqh, (bf*)wql, (bf*)wkh, (bf*)wkl,
        (bf*)wvh, (bf*)wvl, (bf*)woh, (bf*)wol, nW);
    const int nM4 = Bn * Sn * Sn / 4;
    pack_mask<<<(nM4 + 255) / 256, 256>>>((const int4*)mask, (uchar4*)mpk, nM4);

    const float QSCALE = 0.125f * 1.4426950408889634f;   // fold log2e into Q
    dim3 qkvgrid(Dn / 128, Mn / 128, 3);   // (8, 64, 3) — fused Q/K/V
    gemm_qkv<<<qkvgrid, 256, 81920>>>(
        (bf*)iqh, (bf*)iql, (bf*)ikh, (bf*)ikl, (bf*)ivh, (bf*)ivl,
        (bf*)wqh, (bf*)wql, (bf*)wkh, (bf*)wkl, (bf*)wvh, (bf*)wvl,
        bq, bk, bv,
        (bf*)pqh, (bf*)pql, (bf*)pkh, (bf*)pkl, (bf*)pvh, (bf*)pvl,
        QSCALE);

    attn_mma<<<dim3(Sn / 64, Hn, Bn), 128, ATTN_SMEM>>>(
        (const bf*)pqh, (const bf*)pql, (const bf*)pkh, (const bf*)pkl,
        (const bf*)pvh, (const bf*)pvl, (const unsigned char*)mpk, graph,
        (bf*)cxh, (bf*)cxl);

    gemm_o<<<dim3(Dn / 128, Mn / 128), 256, 81920>>>(
        (const bf*)cxh, (const bf*)cxl, (bf*)woh, (bf*)wol, bo, out);
}